// round 3
// baseline (speedup 1.0000x reference)
#include <cuda_runtime.h>
#include <cuda_bf16.h>
#include <math.h>

// Problem constants
#define BB   2
#define TT   2048
#define EE   1024
#define HH   16
#define HS   64
#define ROWS (BB*TT)          // 4096
#define NT   (TT/64)          // 32 tiles of 64

// ---------------- device scratch ----------------
__device__ float g_h1[ROWS*EE];
__device__ float g_q [ROWS*EE];
__device__ float g_k [ROWS*EE];
__device__ float g_v [ROWS*EE];
__device__ float g_attn[ROWS*EE];
__device__ float g_sa [ROWS*EE];
__device__ float g_x1 [ROWS*EE];
__device__ float g_h2 [ROWS*EE];
__device__ float g_f1 [ROWS*4*EE];
__device__ float g_f2 [ROWS*2*EE];
__device__ float g_f3 [ROWS*EE];
__device__ float g_M  [BB*HH*TT];
__device__ float g_L  [BB*HH*TT];

// ---------------- LayerNorm ----------------
__global__ void ln_kernel(const float* __restrict__ x,
                          const float* __restrict__ g,
                          const float* __restrict__ b,
                          float* __restrict__ out) {
    int row = blockIdx.x;
    int tid = threadIdx.x;                 // 256 threads, 4 floats each
    const float* xr = x + (size_t)row * EE;
    float4 v = *(const float4*)(xr + tid * 4);
    float s  = v.x + v.y + v.z + v.w;
    float ss = v.x*v.x + v.y*v.y + v.z*v.z + v.w*v.w;
    __shared__ float sm[32], sm2[32];
    int lane = tid & 31, warp = tid >> 5;
    #pragma unroll
    for (int o = 16; o > 0; o >>= 1) {
        s  += __shfl_down_sync(0xffffffffu, s,  o);
        ss += __shfl_down_sync(0xffffffffu, ss, o);
    }
    if (lane == 0) { sm[warp] = s; sm2[warp] = ss; }
    __syncthreads();
    if (warp == 0) {
        float a = (lane < 8) ? sm[lane]  : 0.f;
        float c = (lane < 8) ? sm2[lane] : 0.f;
        #pragma unroll
        for (int o = 4; o > 0; o >>= 1) {
            a += __shfl_down_sync(0xffffffffu, a, o);
            c += __shfl_down_sync(0xffffffffu, c, o);
        }
        if (lane == 0) { sm[0] = a; sm2[0] = c; }
    }
    __syncthreads();
    float mu  = sm[0]  * (1.0f / EE);
    float var = sm2[0] * (1.0f / EE) - mu * mu;
    float rstd = rsqrtf(var + 1e-5f);
    float4 gg = *(const float4*)(g + tid * 4);
    float4 bb = *(const float4*)(b + tid * 4);
    float4 o;
    o.x = (v.x - mu) * rstd * gg.x + bb.x;
    o.y = (v.y - mu) * rstd * gg.y + bb.y;
    o.z = (v.z - mu) * rstd * gg.z + bb.z;
    o.w = (v.w - mu) * rstd * gg.w + bb.w;
    *(float4*)(out + (size_t)row * EE + tid * 4) = o;
}

// ---------------- SGEMM with fused epilogues ----------------
// BM=128, BN=64, BK=16; 256 threads; per-thread 8x4 micro-tile.
// EPI: 0 = +bias, 1 = gelu(+bias), 2 = other + sigmoid(+bias)*resid
#define GBM 128
#define GBN 64
#define GBK 16

template<int EPI>
__global__ void __launch_bounds__(256, 2)
sgemm(const float* __restrict__ A, const float* __restrict__ Bm,
      const float* __restrict__ bias, float* __restrict__ C,
      int M, int N, int K, size_t bStrideZ, size_t cStrideZ,
      const float* __restrict__ other, const float* __restrict__ resid) {
    __shared__ float As[GBK][GBM + 4];
    __shared__ float Bs[GBK][GBN];
    int z = blockIdx.z;
    const float* Bp = Bm + (size_t)z * bStrideZ;
    float* Cp = C + (size_t)z * cStrideZ;
    int m0 = blockIdx.y * GBM, n0 = blockIdx.x * GBN;
    int tid = threadIdx.x;
    int tx = tid & 15, ty = tid >> 4;

    float acc[8][4];
    #pragma unroll
    for (int i = 0; i < 8; i++)
        #pragma unroll
        for (int j = 0; j < 4; j++) acc[i][j] = 0.f;

    for (int k0 = 0; k0 < K; k0 += GBK) {
        // A tile 128x16 -> transposed store
        #pragma unroll
        for (int i = 0; i < 2; i++) {
            int idx = tid + i * 256;       // float4 index 0..511
            int r = idx >> 2, c4 = idx & 3;
            float4 v = *(const float4*)(A + (size_t)(m0 + r) * K + k0 + c4 * 4);
            As[c4*4+0][r] = v.x; As[c4*4+1][r] = v.y;
            As[c4*4+2][r] = v.z; As[c4*4+3][r] = v.w;
        }
        // B tile 16x64
        {
            int r = tid >> 4, c4 = tid & 15;
            *(float4*)&Bs[r][c4*4] =
                *(const float4*)(Bp + (size_t)(k0 + r) * N + n0 + c4 * 4);
        }
        __syncthreads();
        #pragma unroll
        for (int kk = 0; kk < GBK; kk++) {
            float a[8], b[4];
            *(float4*)&a[0] = *(float4*)&As[kk][ty*8];
            *(float4*)&a[4] = *(float4*)&As[kk][ty*8+4];
            *(float4*)&b[0] = *(float4*)&Bs[kk][tx*4];
            #pragma unroll
            for (int i = 0; i < 8; i++)
                #pragma unroll
                for (int j = 0; j < 4; j++)
                    acc[i][j] += a[i] * b[j];
        }
        __syncthreads();
    }

    float4 bb = make_float4(0.f, 0.f, 0.f, 0.f);
    if (bias) bb = *(const float4*)(bias + n0 + tx * 4);
    #pragma unroll
    for (int i = 0; i < 8; i++) {
        int row = m0 + ty * 8 + i;
        size_t idx = (size_t)row * N + n0 + tx * 4;
        float vv[4] = { acc[i][0] + bb.x, acc[i][1] + bb.y,
                        acc[i][2] + bb.z, acc[i][3] + bb.w };
        float4 o;
        if (EPI == 0) {
            o = make_float4(vv[0], vv[1], vv[2], vv[3]);
        } else if (EPI == 1) {
            #pragma unroll
            for (int j = 0; j < 4; j++)
                vv[j] = 0.5f * vv[j] * (1.0f + erff(vv[j] * 0.70710678118654752f));
            o = make_float4(vv[0], vv[1], vv[2], vv[3]);
        } else {
            float4 ot = *(const float4*)(other + idx);
            float4 rs = *(const float4*)(resid + idx);
            o.x = ot.x + rs.x / (1.0f + __expf(-vv[0]));
            o.y = ot.y + rs.y / (1.0f + __expf(-vv[1]));
            o.z = ot.z + rs.z / (1.0f + __expf(-vv[2]));
            o.w = ot.w + rs.w / (1.0f + __expf(-vv[3]));
        }
        *(float4*)(Cp + idx) = o;
    }
}

// ---------------- Attention pass A: per-row softmax stats ----------------
__global__ void __launch_bounds__(256, 2)
attn_pa(const float* __restrict__ q, const float* __restrict__ k,
        float* __restrict__ Mb, float* __restrict__ Lb) {
    int ttile = blockIdx.x, bh = blockIdx.y;
    int b = bh >> 4, h = bh & 15;
    int t0 = ttile * 64;
    const float* qg = q + ((size_t)h * ROWS + (size_t)b * TT + t0) * HS;
    const float* kg = k + ((size_t)h * ROWS + (size_t)b * TT) * HS;
    __shared__ float qsT[64][68];
    __shared__ float ksT[64][68];
    __shared__ float redM[64][17];
    __shared__ float redL[64][17];
    int tid = threadIdx.x;
    int tx = tid & 15, ty = tid >> 4;

    #pragma unroll
    for (int i = 0; i < 4; i++) {
        int idx = tid + i * 256;          // float4 index
        int r = idx >> 4, c4 = idx & 15;
        float4 v = *(const float4*)(qg + (size_t)r * HS + c4 * 4);
        qsT[c4*4+0][r] = v.x; qsT[c4*4+1][r] = v.y;
        qsT[c4*4+2][r] = v.z; qsT[c4*4+3][r] = v.w;
    }
    float mP[4], lP[4];
    #pragma unroll
    for (int i = 0; i < 4; i++) { mP[i] = -INFINITY; lP[i] = 0.f; }

    for (int st = 0; st <= ttile; st++) {
        __syncthreads();
        #pragma unroll
        for (int i = 0; i < 4; i++) {
            int idx = tid + i * 256;
            int r = idx >> 4, c4 = idx & 15;
            float4 v = *(const float4*)(kg + (size_t)(st*64 + r) * HS + c4 * 4);
            ksT[c4*4+0][r] = v.x; ksT[c4*4+1][r] = v.y;
            ksT[c4*4+2][r] = v.z; ksT[c4*4+3][r] = v.w;
        }
        __syncthreads();
        float acc[4][4];
        #pragma unroll
        for (int i = 0; i < 4; i++)
            #pragma unroll
            for (int j = 0; j < 4; j++) acc[i][j] = 0.f;
        #pragma unroll 16
        for (int kk = 0; kk < 64; kk++) {
            float4 a  = *(float4*)&qsT[kk][ty*4];
            float4 bv = *(float4*)&ksT[kk][tx*4];
            float aa[4] = {a.x, a.y, a.z, a.w};
            float bbv[4] = {bv.x, bv.y, bv.z, bv.w};
            #pragma unroll
            for (int i = 0; i < 4; i++)
                #pragma unroll
                for (int j = 0; j < 4; j++)
                    acc[i][j] += aa[i] * bbv[j];
        }
        int srow = st * 64;
        #pragma unroll
        for (int i = 0; i < 4; i++) {
            int t = t0 + ty * 4 + i;
            #pragma unroll
            for (int j = 0; j < 4; j++) {
                int s = srow + tx * 4 + j;
                if (s <= t) {
                    float sc = acc[i][j] * 0.125f;
                    float mN = fmaxf(mP[i], sc);
                    lP[i] = lP[i] * __expf(mP[i] - mN) + __expf(sc - mN);
                    mP[i] = mN;
                }
            }
        }
    }
    #pragma unroll
    for (int i = 0; i < 4; i++) {
        redM[ty*4+i][tx] = mP[i];
        redL[ty*4+i][tx] = lP[i];
    }
    __syncthreads();
    if (tid < 64) {
        float m = -INFINITY;
        #pragma unroll
        for (int j = 0; j < 16; j++) m = fmaxf(m, redM[tid][j]);
        float l = 0.f;
        #pragma unroll
        for (int j = 0; j < 16; j++) l += redL[tid][j] * __expf(redM[tid][j] - m);
        size_t o = (size_t)bh * TT + t0 + tid;
        Mb[o] = m; Lb[o] = l;
    }
}

// ---------------- Attention pass B: wei + attn ----------------
// dynamic smem: qsT[64*68] + kpT[64*68] + vs[64*68]
__global__ void __launch_bounds__(256, 2)
attn_pb(const float* __restrict__ q, const float* __restrict__ k,
        const float* __restrict__ v,
        const float* __restrict__ Mb, const float* __restrict__ Lb,
        float* __restrict__ wei, float* __restrict__ attn) {
    extern __shared__ float smem[];
    float* qsT = smem;
    float* kpT = smem + 64 * 68;
    float* vs  = smem + 2 * 64 * 68;
#define QS(kk, r) qsT[(kk)*68 + (r)]
#define KP(a, b2) kpT[(a)*68 + (b2)]
#define VS(r, c)  vs[(r)*68 + (c)]
    int ttile = blockIdx.x, bh = blockIdx.y;
    int b = bh >> 4, h = bh & 15;
    int t0 = ttile * 64;
    const float* qg = q + ((size_t)h * ROWS + (size_t)b * TT + t0) * HS;
    const float* kg = k + ((size_t)h * ROWS + (size_t)b * TT) * HS;
    const float* vg = v + ((size_t)h * ROWS + (size_t)b * TT) * HS;
    float* weib = wei + ((size_t)bh * TT + t0) * TT;
    int tid = threadIdx.x;
    int tx = tid & 15, ty = tid >> 4;

    #pragma unroll
    for (int i = 0; i < 4; i++) {
        int idx = tid + i * 256;
        int r = idx >> 4, c4 = idx & 15;
        float4 vv = *(const float4*)(qg + (size_t)r * HS + c4 * 4);
        QS(c4*4+0, r) = vv.x; QS(c4*4+1, r) = vv.y;
        QS(c4*4+2, r) = vv.z; QS(c4*4+3, r) = vv.w;
    }
    float mrow[4], invl[4];
    #pragma unroll
    for (int i = 0; i < 4; i++) {
        size_t o = (size_t)bh * TT + t0 + ty * 4 + i;
        mrow[i] = Mb[o];
        invl[i] = 1.0f / Lb[o];
    }
    float oacc[4][4];
    #pragma unroll
    for (int i = 0; i < 4; i++)
        #pragma unroll
        for (int j = 0; j < 4; j++) oacc[i][j] = 0.f;

    for (int st = 0; st < NT; st++) {
        int sbase = st * 64;
        if (sbase > t0 + 63) {   // fully masked tile: zero-fill wei
            float4 z4 = make_float4(0.f, 0.f, 0.f, 0.f);
            #pragma unroll
            for (int i = 0; i < 4; i++)
                *(float4*)(weib + (size_t)(ty*4+i) * TT + sbase + tx*4) = z4;
            continue;
        }
        __syncthreads();
        #pragma unroll
        for (int i = 0; i < 4; i++) {
            int idx = tid + i * 256;
            int r = idx >> 4, c4 = idx & 15;
            float4 kv = *(const float4*)(kg + (size_t)(sbase + r) * HS + c4 * 4);
            KP(c4*4+0, r) = kv.x; KP(c4*4+1, r) = kv.y;
            KP(c4*4+2, r) = kv.z; KP(c4*4+3, r) = kv.w;
            float4 vv = *(const float4*)(vg + (size_t)(sbase + r) * HS + c4 * 4);
            *(float4*)&VS(r, c4*4) = vv;
        }
        __syncthreads();
        float acc[4][4];
        #pragma unroll
        for (int i = 0; i < 4; i++)
            #pragma unroll
            for (int j = 0; j < 4; j++) acc[i][j] = 0.f;
        #pragma unroll 16
        for (int kk = 0; kk < 64; kk++) {
            float4 a  = *(float4*)&QS(kk, ty*4);
            float4 bv = *(float4*)&KP(kk, tx*4);
            float aa[4] = {a.x, a.y, a.z, a.w};
            float bbv[4] = {bv.x, bv.y, bv.z, bv.w};
            #pragma unroll
            for (int i = 0; i < 4; i++)
                #pragma unroll
                for (int j = 0; j < 4; j++)
                    acc[i][j] += aa[i] * bbv[j];
        }
        float p[4][4];
        #pragma unroll
        for (int i = 0; i < 4; i++) {
            int t = t0 + ty * 4 + i;
            #pragma unroll
            for (int j = 0; j < 4; j++) {
                int s = sbase + tx * 4 + j;
                p[i][j] = (s <= t)
                    ? __expf(acc[i][j] * 0.125f - mrow[i]) * invl[i] : 0.f;
            }
            *(float4*)(weib + (size_t)(ty*4+i) * TT + sbase + tx*4) =
                make_float4(p[i][0], p[i][1], p[i][2], p[i][3]);
        }
        __syncthreads();   // everyone done reading kpT as K
        #pragma unroll
        for (int i = 0; i < 4; i++)
            *(float4*)&KP(ty*4+i, tx*4) =
                make_float4(p[i][0], p[i][1], p[i][2], p[i][3]);
        __syncthreads();
        #pragma unroll 8
        for (int j = 0; j < 64; j++) {
            float4 vv = *(float4*)&VS(j, tx*4);
            #pragma unroll
            for (int i = 0; i < 4; i++) {
                float pp = KP(ty*4+i, j);
                oacc[i][0] += pp * vv.x;
                oacc[i][1] += pp * vv.y;
                oacc[i][2] += pp * vv.z;
                oacc[i][3] += pp * vv.w;
            }
        }
    }
    size_t arow0 = (size_t)b * TT + t0;
    #pragma unroll
    for (int i = 0; i < 4; i++)
        *(float4*)(attn + (arow0 + ty*4 + i) * EE + h * HS + tx * 4) =
            make_float4(oacc[i][0], oacc[i][1], oacc[i][2], oacc[i][3]);
#undef QS
#undef KP
#undef VS
}

// ---------------- launch ----------------
extern "C" void kernel_launch(void* const* d_in, const int* in_sizes, int n_in,
                              void* d_out, int out_size) {
    const float* x      = (const float*)d_in[0];
    const float* wq     = (const float*)d_in[1];
    const float* wk     = (const float*)d_in[2];
    const float* wv     = (const float*)d_in[3];
    const float* wp     = (const float*)d_in[4];
    const float* bp     = (const float*)d_in[5];
    const float* ln1_g  = (const float*)d_in[6];
    const float* ln1_b  = (const float*)d_in[7];
    const float* ln2_g  = (const float*)d_in[8];
    const float* ln2_b  = (const float*)d_in[9];
    const float* w1     = (const float*)d_in[10];
    const float* b1     = (const float*)d_in[11];
    const float* w2     = (const float*)d_in[12];
    const float* b2     = (const float*)d_in[13];
    const float* w3     = (const float*)d_in[14];
    const float* b3     = (const float*)d_in[15];
    const float* wg_att = (const float*)d_in[16];
    const float* bg_att = (const float*)d_in[17];
    const float* wg_ff  = (const float*)d_in[18];
    const float* bg_ff  = (const float*)d_in[19];

    float* out_x   = (float*)d_out;                       // [B,T,E]
    float* out_wei = (float*)d_out + (size_t)ROWS * EE;   // [B,H,T,T]

    float *h1, *q, *k, *v, *attn, *sa, *x1, *h2, *f1, *f2, *f3, *Mb, *Lb;
    cudaGetSymbolAddress((void**)&h1, g_h1);
    cudaGetSymbolAddress((void**)&q,  g_q);
    cudaGetSymbolAddress((void**)&k,  g_k);
    cudaGetSymbolAddress((void**)&v,  g_v);
    cudaGetSymbolAddress((void**)&attn, g_attn);
    cudaGetSymbolAddress((void**)&sa, g_sa);
    cudaGetSymbolAddress((void**)&x1, g_x1);
    cudaGetSymbolAddress((void**)&h2, g_h2);
    cudaGetSymbolAddress((void**)&f1, g_f1);
    cudaGetSymbolAddress((void**)&f2, g_f2);
    cudaGetSymbolAddress((void**)&f3, g_f3);
    cudaGetSymbolAddress((void**)&Mb, g_M);
    cudaGetSymbolAddress((void**)&Lb, g_L);

    int pb_smem = 3 * 64 * 68 * 4;
    cudaFuncSetAttribute(attn_pb, cudaFuncAttributeMaxDynamicSharedMemorySize,
                         pb_smem);

    // 1) h1 = LN1(x)
    ln_kernel<<<ROWS, 256>>>(x, ln1_g, ln1_b, h1);

    // 2) q/k/v per head: [4096,1024] @ [1024,64] x16 heads
    size_t wStrideZ = (size_t)EE * HS;       // per-head weight
    size_t cStrideZ = (size_t)ROWS * HS;     // per-head output
    sgemm<0><<<dim3(1, ROWS/GBM, HH), 256>>>(h1, wq, nullptr, q,
        ROWS, HS, EE, wStrideZ, cStrideZ, nullptr, nullptr);
    sgemm<0><<<dim3(1, ROWS/GBM, HH), 256>>>(h1, wk, nullptr, k,
        ROWS, HS, EE, wStrideZ, cStrideZ, nullptr, nullptr);
    sgemm<0><<<dim3(1, ROWS/GBM, HH), 256>>>(h1, wv, nullptr, v,
        ROWS, HS, EE, wStrideZ, cStrideZ, nullptr, nullptr);

    // 3) attention
    attn_pa<<<dim3(NT, BB*HH), 256>>>(q, k, Mb, Lb);
    attn_pb<<<dim3(NT, BB*HH), 256, pb_smem>>>(q, k, v, Mb, Lb, out_wei, attn);

    // 4) sa = attn @ wp + bp
    sgemm<0><<<dim3(EE/GBN, ROWS/GBM, 1), 256>>>(attn, wp, bp, sa,
        ROWS, EE, EE, 0, 0, nullptr, nullptr);

    // 5) x1 = sa + sigmoid(sa @ wg_att + bg_att) * x
    sgemm<2><<<dim3(EE/GBN, ROWS/GBM, 1), 256>>>(sa, wg_att, bg_att, x1,
        ROWS, EE, EE, 0, 0, sa, x);

    // 6) h2 = LN2(x1)
    ln_kernel<<<ROWS, 256>>>(x1, ln2_g, ln2_b, h2);

    // 7) f1 = gelu(h2 @ w1 + b1)      [4096 x 4096]
    sgemm<1><<<dim3(4*EE/GBN, ROWS/GBM, 1), 256>>>(h2, w1, b1, f1,
        ROWS, 4*EE, EE, 0, 0, nullptr, nullptr);

    // 8) f2 = gelu(f1 @ w2 + b2)      [4096 x 2048], K=4096
    sgemm<1><<<dim3(2*EE/GBN, ROWS/GBM, 1), 256>>>(f1, w2, b2, f2,
        ROWS, 2*EE, 4*EE, 0, 0, nullptr, nullptr);

    // 9) f3 = f2 @ w3 + b3            [4096 x 1024], K=2048
    sgemm<0><<<dim3(EE/GBN, ROWS/GBM, 1), 256>>>(f2, w3, b3, f3,
        ROWS, EE, 2*EE, 0, 0, nullptr, nullptr);

    // 10) out_x = f3 + sigmoid(f3 @ wg_ff + bg_ff) * x1
    sgemm<2><<<dim3(EE/GBN, ROWS/GBM, 1), 256>>>(f3, wg_ff, bg_ff, out_x,
        ROWS, EE, 2*EE/2, 0, 0, f3, x1);
}

// round 4
// speedup vs baseline: 1.9174x; 1.9174x over previous
#include <cuda_runtime.h>
#include <cuda_bf16.h>
#include <math.h>

// Problem constants
#define BB   2
#define TT   2048
#define EE   1024
#define HH   16
#define HS   64
#define ROWS (BB*TT)          // 4096
#define NT   (TT/64)          // 32 tiles of 64

// ---------------- device scratch ----------------
__device__ float g_h1[ROWS*EE];
__device__ float g_q [ROWS*EE];
__device__ float g_k [ROWS*EE];
__device__ float g_v [ROWS*EE];
__device__ float g_attn[ROWS*EE];
__device__ float g_sa [ROWS*EE];
__device__ float g_x1 [ROWS*EE];
__device__ float g_h2 [ROWS*EE];
__device__ float g_f1 [ROWS*4*EE];
__device__ float g_f2 [ROWS*2*EE];
__device__ float g_f3 [ROWS*EE];
__device__ float g_M  [BB*HH*TT];
__device__ float g_L  [BB*HH*TT];

// ---------------- LayerNorm ----------------
__global__ void ln_kernel(const float* __restrict__ x,
                          const float* __restrict__ g,
                          const float* __restrict__ b,
                          float* __restrict__ out) {
    int row = blockIdx.x;
    int tid = threadIdx.x;                 // 256 threads, 4 floats each
    const float* xr = x + (size_t)row * EE;
    float4 v = *(const float4*)(xr + tid * 4);
    float s  = v.x + v.y + v.z + v.w;
    float ss = v.x*v.x + v.y*v.y + v.z*v.z + v.w*v.w;
    __shared__ float sm[32], sm2[32];
    int lane = tid & 31, warp = tid >> 5;
    #pragma unroll
    for (int o = 16; o > 0; o >>= 1) {
        s  += __shfl_down_sync(0xffffffffu, s,  o);
        ss += __shfl_down_sync(0xffffffffu, ss, o);
    }
    if (lane == 0) { sm[warp] = s; sm2[warp] = ss; }
    __syncthreads();
    if (warp == 0) {
        float a = (lane < 8) ? sm[lane]  : 0.f;
        float c = (lane < 8) ? sm2[lane] : 0.f;
        #pragma unroll
        for (int o = 4; o > 0; o >>= 1) {
            a += __shfl_down_sync(0xffffffffu, a, o);
            c += __shfl_down_sync(0xffffffffu, c, o);
        }
        if (lane == 0) { sm[0] = a; sm2[0] = c; }
    }
    __syncthreads();
    float mu  = sm[0]  * (1.0f / EE);
    float var = sm2[0] * (1.0f / EE) - mu * mu;
    float rstd = rsqrtf(var + 1e-5f);
    float4 gg = *(const float4*)(g + tid * 4);
    float4 bb = *(const float4*)(b + tid * 4);
    float4 o;
    o.x = (v.x - mu) * rstd * gg.x + bb.x;
    o.y = (v.y - mu) * rstd * gg.y + bb.y;
    o.z = (v.z - mu) * rstd * gg.z + bb.z;
    o.w = (v.w - mu) * rstd * gg.w + bb.w;
    *(float4*)(out + (size_t)row * EE + tid * 4) = o;
}

// ---------------- tf32 helpers ----------------
__device__ __forceinline__ unsigned f2tf32(float f) {
    unsigned u;
    asm("cvt.rna.tf32.f32 %0, %1;" : "=r"(u) : "f"(f));
    return u;
}

__device__ __forceinline__ void mma_tf32(float* c, const unsigned* a,
                                         const unsigned* b) {
    asm volatile(
        "mma.sync.aligned.m16n8k8.row.col.f32.tf32.tf32.f32 "
        "{%0,%1,%2,%3}, {%4,%5,%6,%7}, {%8,%9}, {%0,%1,%2,%3};"
        : "+f"(c[0]), "+f"(c[1]), "+f"(c[2]), "+f"(c[3])
        : "r"(a[0]), "r"(a[1]), "r"(a[2]), "r"(a[3]),
          "r"(b[0]), "r"(b[1]));
}

// ---------------- tf32 MMA GEMM with fused epilogues ----------------
// BM=128, BK=16, BN template (128 or 64). Warp tile 64x32 (4x4 m16n8k8).
// BN=128: 8 warps (2Mx4N), 256 thr. BN=64: 4 warps (2Mx2N), 128 thr.
// EPI: 0 = +bias, 1 = gelu(+bias), 2 = other + sigmoid(+bias)*resid
#define BMM 128
#define BKK 16

template<int BN, int EPI>
__global__ void __launch_bounds__(BN == 128 ? 256 : 128, 2)
mma_gemm(const float* __restrict__ A, const float* __restrict__ Bm,
         const float* __restrict__ bias, float* __restrict__ C,
         int M, int N, int K, size_t bStrideZ, size_t cStrideZ,
         const float* __restrict__ other, const float* __restrict__ resid) {
    constexpr int THREADS = (BN == 128) ? 256 : 128;
    constexpr int NWN = BN / 32;                    // warps along N
    constexpr int LA = 512 / THREADS;               // A float4 per thread
    constexpr int LB = (BKK * BN / 4) / THREADS;    // B float4 per thread
    constexpr int BNQ = BN / 4;                     // B float4 per k-row

    __shared__ unsigned As[BKK][BMM + 8];
    __shared__ unsigned Bs[BKK][BN + 8];

    int z = blockIdx.z;
    const float* Bp = Bm + (size_t)z * bStrideZ;
    float* Cp = C + (size_t)z * cStrideZ;
    int m0 = blockIdx.y * BMM, n0 = blockIdx.x * BN;
    int tid  = threadIdx.x;
    int lane = tid & 31, warp = tid >> 5;
    int wm = warp / NWN, wn = warp % NWN;

    float acc[4][4][4];
    #pragma unroll
    for (int i = 0; i < 4; i++)
        #pragma unroll
        for (int j = 0; j < 4; j++)
            #pragma unroll
            for (int l = 0; l < 4; l++) acc[i][j][l] = 0.f;

    float4 ra[LA], rb[LB];
    // prefetch k0 = 0
    #pragma unroll
    for (int i = 0; i < LA; i++) {
        int idx = tid + i * THREADS;
        int r = idx >> 2, c4 = idx & 3;
        ra[i] = *(const float4*)(A + (size_t)(m0 + r) * K + c4 * 4);
    }
    #pragma unroll
    for (int i = 0; i < LB; i++) {
        int idx = tid + i * THREADS;
        int r = idx / BNQ, c4 = idx % BNQ;
        rb[i] = *(const float4*)(Bp + (size_t)r * N + n0 + c4 * 4);
    }

    for (int k0 = 0; k0 < K; k0 += BKK) {
        // stage regs -> smem (convert to tf32)
        #pragma unroll
        for (int i = 0; i < LA; i++) {
            int idx = tid + i * THREADS;
            int r = idx >> 2, c4 = idx & 3;
            As[c4*4+0][r] = f2tf32(ra[i].x);
            As[c4*4+1][r] = f2tf32(ra[i].y);
            As[c4*4+2][r] = f2tf32(ra[i].z);
            As[c4*4+3][r] = f2tf32(ra[i].w);
        }
        #pragma unroll
        for (int i = 0; i < LB; i++) {
            int idx = tid + i * THREADS;
            int r = idx / BNQ, c4 = idx % BNQ;
            uint4 u = make_uint4(f2tf32(rb[i].x), f2tf32(rb[i].y),
                                 f2tf32(rb[i].z), f2tf32(rb[i].w));
            *(uint4*)&Bs[r][c4 * 4] = u;
        }
        __syncthreads();

        // prefetch next k-block
        int kn = k0 + BKK;
        if (kn < K) {
            #pragma unroll
            for (int i = 0; i < LA; i++) {
                int idx = tid + i * THREADS;
                int r = idx >> 2, c4 = idx & 3;
                ra[i] = *(const float4*)(A + (size_t)(m0 + r) * K + kn + c4*4);
            }
            #pragma unroll
            for (int i = 0; i < LB; i++) {
                int idx = tid + i * THREADS;
                int r = idx / BNQ, c4 = idx % BNQ;
                rb[i] = *(const float4*)(Bp + (size_t)(kn + r) * N + n0 + c4*4);
            }
        }

        // compute 2 x k8
        #pragma unroll
        for (int ks = 0; ks < BKK; ks += 8) {
            int lk = ks + (lane & 3);
            int lm = lane >> 2;
            unsigned a[4][4], b[4][2];
            #pragma unroll
            for (int mi = 0; mi < 4; mi++) {
                int m = wm * 64 + mi * 16 + lm;
                a[mi][0] = As[lk][m];
                a[mi][1] = As[lk][m + 8];
                a[mi][2] = As[lk + 4][m];
                a[mi][3] = As[lk + 4][m + 8];
            }
            #pragma unroll
            for (int ni = 0; ni < 4; ni++) {
                int n = wn * 32 + ni * 8 + lm;
                b[ni][0] = Bs[lk][n];
                b[ni][1] = Bs[lk + 4][n];
            }
            #pragma unroll
            for (int mi = 0; mi < 4; mi++)
                #pragma unroll
                for (int ni = 0; ni < 4; ni++)
                    mma_tf32(acc[mi][ni], a[mi], b[ni]);
        }
        __syncthreads();
    }

    // ---------------- epilogue ----------------
    int gm = m0 + wm * 64;
    int gn = n0 + wn * 32;
    #pragma unroll
    for (int mi = 0; mi < 4; mi++) {
        #pragma unroll
        for (int half = 0; half < 2; half++) {
            int row = gm + mi * 16 + (lane >> 2) + half * 8;
            #pragma unroll
            for (int ni = 0; ni < 4; ni++) {
                int col = gn + ni * 8 + (lane & 3) * 2;
                float v0 = acc[mi][ni][half * 2 + 0];
                float v1 = acc[mi][ni][half * 2 + 1];
                if (bias) { v0 += bias[col]; v1 += bias[col + 1]; }
                size_t idx = (size_t)row * N + col;
                float2 o;
                if (EPI == 0) {
                    o = make_float2(v0, v1);
                } else if (EPI == 1) {
                    o.x = 0.5f * v0 * (1.0f + erff(v0 * 0.70710678118654752f));
                    o.y = 0.5f * v1 * (1.0f + erff(v1 * 0.70710678118654752f));
                } else {
                    float2 ot = *(const float2*)(other + idx);
                    float2 rs = *(const float2*)(resid + idx);
                    o.x = ot.x + rs.x / (1.0f + __expf(-v0));
                    o.y = ot.y + rs.y / (1.0f + __expf(-v1));
                }
                *(float2*)(Cp + idx) = o;
            }
        }
    }
}

// ---------------- Attention pass A: per-row softmax stats ----------------
__global__ void __launch_bounds__(256, 2)
attn_pa(const float* __restrict__ q, const float* __restrict__ k,
        float* __restrict__ Mb, float* __restrict__ Lb) {
    int ttile = blockIdx.x, bh = blockIdx.y;
    int b = bh >> 4, h = bh & 15;
    int t0 = ttile * 64;
    const float* qg = q + ((size_t)h * ROWS + (size_t)b * TT + t0) * HS;
    const float* kg = k + ((size_t)h * ROWS + (size_t)b * TT) * HS;
    __shared__ float qsT[64][68];
    __shared__ float ksT[64][68];
    __shared__ float redM[64][17];
    __shared__ float redL[64][17];
    int tid = threadIdx.x;
    int tx = tid & 15, ty = tid >> 4;

    #pragma unroll
    for (int i = 0; i < 4; i++) {
        int idx = tid + i * 256;          // float4 index
        int r = idx >> 4, c4 = idx & 15;
        float4 v = *(const float4*)(qg + (size_t)r * HS + c4 * 4);
        qsT[c4*4+0][r] = v.x; qsT[c4*4+1][r] = v.y;
        qsT[c4*4+2][r] = v.z; qsT[c4*4+3][r] = v.w;
    }
    float mP[4], lP[4];
    #pragma unroll
    for (int i = 0; i < 4; i++) { mP[i] = -INFINITY; lP[i] = 0.f; }

    for (int st = 0; st <= ttile; st++) {
        __syncthreads();
        #pragma unroll
        for (int i = 0; i < 4; i++) {
            int idx = tid + i * 256;
            int r = idx >> 4, c4 = idx & 15;
            float4 v = *(const float4*)(kg + (size_t)(st*64 + r) * HS + c4 * 4);
            ksT[c4*4+0][r] = v.x; ksT[c4*4+1][r] = v.y;
            ksT[c4*4+2][r] = v.z; ksT[c4*4+3][r] = v.w;
        }
        __syncthreads();
        float acc[4][4];
        #pragma unroll
        for (int i = 0; i < 4; i++)
            #pragma unroll
            for (int j = 0; j < 4; j++) acc[i][j] = 0.f;
        #pragma unroll 16
        for (int kk = 0; kk < 64; kk++) {
            float4 a  = *(float4*)&qsT[kk][ty*4];
            float4 bv = *(float4*)&ksT[kk][tx*4];
            float aa[4] = {a.x, a.y, a.z, a.w};
            float bbv[4] = {bv.x, bv.y, bv.z, bv.w};
            #pragma unroll
            for (int i = 0; i < 4; i++)
                #pragma unroll
                for (int j = 0; j < 4; j++)
                    acc[i][j] += aa[i] * bbv[j];
        }
        int srow = st * 64;
        #pragma unroll
        for (int i = 0; i < 4; i++) {
            int t = t0 + ty * 4 + i;
            #pragma unroll
            for (int j = 0; j < 4; j++) {
                int s = srow + tx * 4 + j;
                if (s <= t) {
                    float sc = acc[i][j] * 0.125f;
                    float mN = fmaxf(mP[i], sc);
                    lP[i] = lP[i] * __expf(mP[i] - mN) + __expf(sc - mN);
                    mP[i] = mN;
                }
            }
        }
    }
    #pragma unroll
    for (int i = 0; i < 4; i++) {
        redM[ty*4+i][tx] = mP[i];
        redL[ty*4+i][tx] = lP[i];
    }
    __syncthreads();
    if (tid < 64) {
        float m = -INFINITY;
        #pragma unroll
        for (int j = 0; j < 16; j++) m = fmaxf(m, redM[tid][j]);
        float l = 0.f;
        #pragma unroll
        for (int j = 0; j < 16; j++) l += redL[tid][j] * __expf(redM[tid][j] - m);
        size_t o = (size_t)bh * TT + t0 + tid;
        Mb[o] = m; Lb[o] = l;
    }
}

// ---------------- Attention pass B: wei + attn ----------------
// dynamic smem: qsT[64*68] + kpT[64*68] + vs[64*68]
__global__ void __launch_bounds__(256, 2)
attn_pb(const float* __restrict__ q, const float* __restrict__ k,
        const float* __restrict__ v,
        const float* __restrict__ Mb, const float* __restrict__ Lb,
        float* __restrict__ wei, float* __restrict__ attn) {
    extern __shared__ float smem[];
    float* qsT = smem;
    float* kpT = smem + 64 * 68;
    float* vs  = smem + 2 * 64 * 68;
#define QS(kk, r) qsT[(kk)*68 + (r)]
#define KP(a, b2) kpT[(a)*68 + (b2)]
#define VS(r, c)  vs[(r)*68 + (c)]
    int ttile = blockIdx.x, bh = blockIdx.y;
    int b = bh >> 4, h = bh & 15;
    int t0 = ttile * 64;
    const float* qg = q + ((size_t)h * ROWS + (size_t)b * TT + t0) * HS;
    const float* kg = k + ((size_t)h * ROWS + (size_t)b * TT) * HS;
    const float* vg = v + ((size_t)h * ROWS + (size_t)b * TT) * HS;
    float* weib = wei + ((size_t)bh * TT + t0) * TT;
    int tid = threadIdx.x;
    int tx = tid & 15, ty = tid >> 4;

    #pragma unroll
    for (int i = 0; i < 4; i++) {
        int idx = tid + i * 256;
        int r = idx >> 4, c4 = idx & 15;
        float4 vv = *(const float4*)(qg + (size_t)r * HS + c4 * 4);
        QS(c4*4+0, r) = vv.x; QS(c4*4+1, r) = vv.y;
        QS(c4*4+2, r) = vv.z; QS(c4*4+3, r) = vv.w;
    }
    float mrow[4], invl[4];
    #pragma unroll
    for (int i = 0; i < 4; i++) {
        size_t o = (size_t)bh * TT + t0 + ty * 4 + i;
        mrow[i] = Mb[o];
        invl[i] = 1.0f / Lb[o];
    }
    float oacc[4][4];
    #pragma unroll
    for (int i = 0; i < 4; i++)
        #pragma unroll
        for (int j = 0; j < 4; j++) oacc[i][j] = 0.f;

    for (int st = 0; st < NT; st++) {
        int sbase = st * 64;
        if (sbase > t0 + 63) {   // fully masked tile: zero-fill wei
            float4 z4 = make_float4(0.f, 0.f, 0.f, 0.f);
            #pragma unroll
            for (int i = 0; i < 4; i++)
                *(float4*)(weib + (size_t)(ty*4+i) * TT + sbase + tx*4) = z4;
            continue;
        }
        __syncthreads();
        #pragma unroll
        for (int i = 0; i < 4; i++) {
            int idx = tid + i * 256;
            int r = idx >> 4, c4 = idx & 15;
            float4 kv = *(const float4*)(kg + (size_t)(sbase + r) * HS + c4 * 4);
            KP(c4*4+0, r) = kv.x; KP(c4*4+1, r) = kv.y;
            KP(c4*4+2, r) = kv.z; KP(c4*4+3, r) = kv.w;
            float4 vv = *(const float4*)(vg + (size_t)(sbase + r) * HS + c4 * 4);
            *(float4*)&VS(r, c4*4) = vv;
        }
        __syncthreads();
        float acc[4][4];
        #pragma unroll
        for (int i = 0; i < 4; i++)
            #pragma unroll
            for (int j = 0; j < 4; j++) acc[i][j] = 0.f;
        #pragma unroll 16
        for (int kk = 0; kk < 64; kk++) {
            float4 a  = *(float4*)&QS(kk, ty*4);
            float4 bv = *(float4*)&KP(kk, tx*4);
            float aa[4] = {a.x, a.y, a.z, a.w};
            float bbv[4] = {bv.x, bv.y, bv.z, bv.w};
            #pragma unroll
            for (int i = 0; i < 4; i++)
                #pragma unroll
                for (int j = 0; j < 4; j++)
                    acc[i][j] += aa[i] * bbv[j];
        }
        float p[4][4];
        #pragma unroll
        for (int i = 0; i < 4; i++) {
            int t = t0 + ty * 4 + i;
            #pragma unroll
            for (int j = 0; j < 4; j++) {
                int s = sbase + tx * 4 + j;
                p[i][j] = (s <= t)
                    ? __expf(acc[i][j] * 0.125f - mrow[i]) * invl[i] : 0.f;
            }
            *(float4*)(weib + (size_t)(ty*4+i) * TT + sbase + tx*4) =
                make_float4(p[i][0], p[i][1], p[i][2], p[i][3]);
        }
        __syncthreads();   // everyone done reading kpT as K
        #pragma unroll
        for (int i = 0; i < 4; i++)
            *(float4*)&KP(ty*4+i, tx*4) =
                make_float4(p[i][0], p[i][1], p[i][2], p[i][3]);
        __syncthreads();
        #pragma unroll 8
        for (int j = 0; j < 64; j++) {
            float4 vv = *(float4*)&VS(j, tx*4);
            #pragma unroll
            for (int i = 0; i < 4; i++) {
                float pp = KP(ty*4+i, j);
                oacc[i][0] += pp * vv.x;
                oacc[i][1] += pp * vv.y;
                oacc[i][2] += pp * vv.z;
                oacc[i][3] += pp * vv.w;
            }
        }
    }
    size_t arow0 = (size_t)b * TT + t0;
    #pragma unroll
    for (int i = 0; i < 4; i++)
        *(float4*)(attn + (arow0 + ty*4 + i) * EE + h * HS + tx * 4) =
            make_float4(oacc[i][0], oacc[i][1], oacc[i][2], oacc[i][3]);
#undef QS
#undef KP
#undef VS
}

// ---------------- launch ----------------
extern "C" void kernel_launch(void* const* d_in, const int* in_sizes, int n_in,
                              void* d_out, int out_size) {
    const float* x      = (const float*)d_in[0];
    const float* wq     = (const float*)d_in[1];
    const float* wk     = (const float*)d_in[2];
    const float* wv     = (const float*)d_in[3];
    const float* wp     = (const float*)d_in[4];
    const float* bp     = (const float*)d_in[5];
    const float* ln1_g  = (const float*)d_in[6];
    const float* ln1_b  = (const float*)d_in[7];
    const float* ln2_g  = (const float*)d_in[8];
    const float* ln2_b  = (const float*)d_in[9];
    const float* w1     = (const float*)d_in[10];
    const float* b1     = (const float*)d_in[11];
    const float* w2     = (const float*)d_in[12];
    const float* b2     = (const float*)d_in[13];
    const float* w3     = (const float*)d_in[14];
    const float* b3     = (const float*)d_in[15];
    const float* wg_att = (const float*)d_in[16];
    const float* bg_att = (const float*)d_in[17];
    const float* wg_ff  = (const float*)d_in[18];
    const float* bg_ff  = (const float*)d_in[19];

    float* out_x   = (float*)d_out;                       // [B,T,E]
    float* out_wei = (float*)d_out + (size_t)ROWS * EE;   // [B,H,T,T]

    float *h1, *q, *k, *v, *attn, *sa, *x1, *h2, *f1, *f2, *f3, *Mb, *Lb;
    cudaGetSymbolAddress((void**)&h1, g_h1);
    cudaGetSymbolAddress((void**)&q,  g_q);
    cudaGetSymbolAddress((void**)&k,  g_k);
    cudaGetSymbolAddress((void**)&v,  g_v);
    cudaGetSymbolAddress((void**)&attn, g_attn);
    cudaGetSymbolAddress((void**)&sa, g_sa);
    cudaGetSymbolAddress((void**)&x1, g_x1);
    cudaGetSymbolAddress((void**)&h2, g_h2);
    cudaGetSymbolAddress((void**)&f1, g_f1);
    cudaGetSymbolAddress((void**)&f2, g_f2);
    cudaGetSymbolAddress((void**)&f3, g_f3);
    cudaGetSymbolAddress((void**)&Mb, g_M);
    cudaGetSymbolAddress((void**)&Lb, g_L);

    int pb_smem = 3 * 64 * 68 * 4;
    cudaFuncSetAttribute(attn_pb, cudaFuncAttributeMaxDynamicSharedMemorySize,
                         pb_smem);

    // 1) h1 = LN1(x)
    ln_kernel<<<ROWS, 256>>>(x, ln1_g, ln1_b, h1);

    // 2) q/k/v per head: [4096,1024] @ [1024,64] x16 heads (tf32 MMA)
    size_t wStrideZ = (size_t)EE * HS;       // per-head weight
    size_t cStrideZ = (size_t)ROWS * HS;     // per-head output
    mma_gemm<64,0><<<dim3(1, ROWS/BMM, HH), 128>>>(h1, wq, nullptr, q,
        ROWS, HS, EE, wStrideZ, cStrideZ, nullptr, nullptr);
    mma_gemm<64,0><<<dim3(1, ROWS/BMM, HH), 128>>>(h1, wk, nullptr, k,
        ROWS, HS, EE, wStrideZ, cStrideZ, nullptr, nullptr);
    mma_gemm<64,0><<<dim3(1, ROWS/BMM, HH), 128>>>(h1, wv, nullptr, v,
        ROWS, HS, EE, wStrideZ, cStrideZ, nullptr, nullptr);

    // 3) attention
    attn_pa<<<dim3(NT, BB*HH), 256>>>(q, k, Mb, Lb);
    attn_pb<<<dim3(NT, BB*HH), 256, pb_smem>>>(q, k, v, Mb, Lb, out_wei, attn);

    // 4) sa = attn @ wp + bp
    mma_gemm<128,0><<<dim3(EE/128, ROWS/BMM, 1), 256>>>(attn, wp, bp, sa,
        ROWS, EE, EE, 0, 0, nullptr, nullptr);

    // 5) x1 = sa + sigmoid(sa @ wg_att + bg_att) * x
    mma_gemm<128,2><<<dim3(EE/128, ROWS/BMM, 1), 256>>>(sa, wg_att, bg_att, x1,
        ROWS, EE, EE, 0, 0, sa, x);

    // 6) h2 = LN2(x1)
    ln_kernel<<<ROWS, 256>>>(x1, ln2_g, ln2_b, h2);

    // 7) f1 = gelu(h2 @ w1 + b1)      [4096 x 4096]
    mma_gemm<128,1><<<dim3(4*EE/128, ROWS/BMM, 1), 256>>>(h2, w1, b1, f1,
        ROWS, 4*EE, EE, 0, 0, nullptr, nullptr);

    // 8) f2 = gelu(f1 @ w2 + b2)      [4096 x 2048], K=4096
    mma_gemm<128,1><<<dim3(2*EE/128, ROWS/BMM, 1), 256>>>(f1, w2, b2, f2,
        ROWS, 2*EE, 4*EE, 0, 0, nullptr, nullptr);

    // 9) f3 = f2 @ w3 + b3            [4096 x 1024], K=2048
    mma_gemm<128,0><<<dim3(EE/128, ROWS/BMM, 1), 256>>>(f2, w3, b3, f3,
        ROWS, EE, 2*EE, 0, 0, nullptr, nullptr);

    // 10) out_x = f3 + sigmoid(f3 @ wg_ff + bg_ff) * x1   (K = E)
    mma_gemm<128,2><<<dim3(EE/128, ROWS/BMM, 1), 256>>>(f3, wg_ff, bg_ff, out_x,
        ROWS, EE, EE, 0, 0, f3, x1);
}

// round 5
// speedup vs baseline: 2.1198x; 1.1056x over previous
#include <cuda_runtime.h>
#include <cuda_bf16.h>
#include <math.h>

// Problem constants
#define BB   2
#define TT   2048
#define EE   1024
#define HH   16
#define HS   64
#define ROWS (BB*TT)          // 4096
#define NT   (TT/64)          // 32 tiles of 64

// ---------------- device scratch ----------------
__device__ float g_h1[ROWS*EE];
__device__ float g_q [ROWS*EE];
__device__ float g_k [ROWS*EE];
__device__ float g_v [ROWS*EE];
__device__ float g_attn[ROWS*EE];
__device__ float g_sa [ROWS*EE];
__device__ float g_x1 [ROWS*EE];
__device__ float g_h2 [ROWS*EE];
__device__ float g_f1 [ROWS*4*EE];
__device__ float g_f2 [ROWS*2*EE];
__device__ float g_f3 [ROWS*EE];
__device__ float g_M  [BB*HH*TT];
__device__ float g_L  [BB*HH*TT];

// ---------------- LayerNorm ----------------
__global__ void ln_kernel(const float* __restrict__ x,
                          const float* __restrict__ g,
                          const float* __restrict__ b,
                          float* __restrict__ out) {
    int row = blockIdx.x;
    int tid = threadIdx.x;                 // 256 threads, 4 floats each
    const float* xr = x + (size_t)row * EE;
    float4 v = *(const float4*)(xr + tid * 4);
    float s  = v.x + v.y + v.z + v.w;
    float ss = v.x*v.x + v.y*v.y + v.z*v.z + v.w*v.w;
    __shared__ float sm[32], sm2[32];
    int lane = tid & 31, warp = tid >> 5;
    #pragma unroll
    for (int o = 16; o > 0; o >>= 1) {
        s  += __shfl_down_sync(0xffffffffu, s,  o);
        ss += __shfl_down_sync(0xffffffffu, ss, o);
    }
    if (lane == 0) { sm[warp] = s; sm2[warp] = ss; }
    __syncthreads();
    if (warp == 0) {
        float a = (lane < 8) ? sm[lane]  : 0.f;
        float c = (lane < 8) ? sm2[lane] : 0.f;
        #pragma unroll
        for (int o = 4; o > 0; o >>= 1) {
            a += __shfl_down_sync(0xffffffffu, a, o);
            c += __shfl_down_sync(0xffffffffu, c, o);
        }
        if (lane == 0) { sm[0] = a; sm2[0] = c; }
    }
    __syncthreads();
    float mu  = sm[0]  * (1.0f / EE);
    float var = sm2[0] * (1.0f / EE) - mu * mu;
    float rstd = rsqrtf(var + 1e-5f);
    float4 gg = *(const float4*)(g + tid * 4);
    float4 bb = *(const float4*)(b + tid * 4);
    float4 o;
    o.x = (v.x - mu) * rstd * gg.x + bb.x;
    o.y = (v.y - mu) * rstd * gg.y + bb.y;
    o.z = (v.z - mu) * rstd * gg.z + bb.z;
    o.w = (v.w - mu) * rstd * gg.w + bb.w;
    *(float4*)(out + (size_t)row * EE + tid * 4) = o;
}

// ---------------- tf32 / cp.async helpers ----------------
__device__ __forceinline__ unsigned f2tf32(float f) {
    unsigned u;
    asm("cvt.rna.tf32.f32 %0, %1;" : "=r"(u) : "f"(f));
    return u;
}

__device__ __forceinline__ void mma_tf32(float* c, const unsigned* a,
                                         const unsigned* b) {
    asm volatile(
        "mma.sync.aligned.m16n8k8.row.col.f32.tf32.tf32.f32 "
        "{%0,%1,%2,%3}, {%4,%5,%6,%7}, {%8,%9}, {%0,%1,%2,%3};"
        : "+f"(c[0]), "+f"(c[1]), "+f"(c[2]), "+f"(c[3])
        : "r"(a[0]), "r"(a[1]), "r"(a[2]), "r"(a[3]),
          "r"(b[0]), "r"(b[1]));
}

__device__ __forceinline__ void cp_async16(void* smem_dst, const void* gsrc) {
    unsigned s = (unsigned)__cvta_generic_to_shared(smem_dst);
    asm volatile("cp.async.cg.shared.global [%0], [%1], 16;"
                 :: "r"(s), "l"(gsrc));
}
#define CP_COMMIT() asm volatile("cp.async.commit_group;" ::: "memory")
#define CP_WAIT0()  asm volatile("cp.async.wait_group 0;" ::: "memory")

// ---------------- tf32 MMA GEMM, cp.async double-buffered ----------------
// BM=128, BK=16, BN in {128, 64}. Warp tile 64x32 (4x4 m16n8k8 frags).
// Smem holds RAW fp32 (cvt at fragment load). A [m][k] pitch 20, B [k][n]
// pitch BN+8 — both conflict-free for the fragment access patterns.
// EPI: 0 = +bias, 1 = gelu(+bias), 2 = other + sigmoid(+bias)*resid
// QKV: 1 = z selects among (B0,C0)/(B1,C1)/(B2,C2) x 16 heads
#define BMM 128
#define BKK 16

template<int BN, int EPI, int QKV>
__global__ void __launch_bounds__((BN == 128) ? 256 : 128, (BN == 128) ? 2 : 3)
mma_gemm(const float* __restrict__ A,
         const float* __restrict__ B0, const float* __restrict__ B1,
         const float* __restrict__ B2,
         const float* __restrict__ bias,
         float* __restrict__ C0, float* __restrict__ C1,
         float* __restrict__ C2,
         int M, int N, int K, size_t bStrideZ, size_t cStrideZ,
         const float* __restrict__ other, const float* __restrict__ resid) {
    constexpr int THREADS = (BN == 128) ? 256 : 128;
    constexpr int NWN = BN / 32;            // warps along N
    constexpr int AP  = 20;                 // A smem pitch (words)
    constexpr int BP  = BN + 8;             // B smem pitch (words)
    constexpr int LA  = 512 / THREADS;      // A float4 per thread per stage
    constexpr int LB  = (BKK * BN / 4) / THREADS;
    constexpr int BNQ = BN / 4;

    __shared__ float As[2][BMM * AP];
    __shared__ float Bs[2][BKK * BP];

    const float* Bp;
    float* Cp;
    if (QKV) {
        int zz = blockIdx.z;
        int which = zz >> 4, head = zz & 15;
        const float* Bsel = (which == 0) ? B0 : ((which == 1) ? B1 : B2);
        float*       Csel = (which == 0) ? C0 : ((which == 1) ? C1 : C2);
        Bp = Bsel + (size_t)head * bStrideZ;
        Cp = Csel + (size_t)head * cStrideZ;
    } else {
        Bp = B0; Cp = C0;
    }

    int m0 = blockIdx.y * BMM, n0 = blockIdx.x * BN;
    int tid  = threadIdx.x;
    int lane = tid & 31, warp = tid >> 5;
    int wm = warp / NWN, wn = warp % NWN;

    float acc[4][4][4];
    #pragma unroll
    for (int i = 0; i < 4; i++)
        #pragma unroll
        for (int j = 0; j < 4; j++)
            #pragma unroll
            for (int l = 0; l < 4; l++) acc[i][j][l] = 0.f;

    // --- stage k-block into smem buffer s via cp.async ---
    auto stage = [&](int s, int k0) {
        #pragma unroll
        for (int i = 0; i < LA; i++) {
            int idx = tid + i * THREADS;
            int r = idx >> 2, c4 = idx & 3;
            cp_async16(&As[s][r * AP + c4 * 4],
                       A + (size_t)(m0 + r) * K + k0 + c4 * 4);
        }
        #pragma unroll
        for (int i = 0; i < LB; i++) {
            int idx = tid + i * THREADS;
            int r = idx / BNQ, c4 = idx % BNQ;
            cp_async16(&Bs[s][r * BP + c4 * 4],
                       Bp + (size_t)(k0 + r) * N + n0 + c4 * 4);
        }
    };

    stage(0, 0);
    CP_COMMIT();

    int nk = K / BKK;
    for (int it = 0; it < nk; it++) {
        CP_WAIT0();
        __syncthreads();
        if (it + 1 < nk) {
            stage((it + 1) & 1, (it + 1) * BKK);
            CP_COMMIT();
        }
        int s = it & 1;
        #pragma unroll
        for (int ks = 0; ks < BKK; ks += 8) {
            int lk = ks + (lane & 3);
            int lm = lane >> 2;
            unsigned a[4][4], b[4][2];
            #pragma unroll
            for (int mi = 0; mi < 4; mi++) {
                int m = wm * 64 + mi * 16 + lm;
                a[mi][0] = f2tf32(As[s][m * AP + lk]);
                a[mi][1] = f2tf32(As[s][(m + 8) * AP + lk]);
                a[mi][2] = f2tf32(As[s][m * AP + lk + 4]);
                a[mi][3] = f2tf32(As[s][(m + 8) * AP + lk + 4]);
            }
            #pragma unroll
            for (int ni = 0; ni < 4; ni++) {
                int n = wn * 32 + ni * 8 + lm;
                b[ni][0] = f2tf32(Bs[s][lk * BP + n]);
                b[ni][1] = f2tf32(Bs[s][(lk + 4) * BP + n]);
            }
            #pragma unroll
            for (int mi = 0; mi < 4; mi++)
                #pragma unroll
                for (int ni = 0; ni < 4; ni++)
                    mma_tf32(acc[mi][ni], a[mi], b[ni]);
        }
    }

    // ---------------- epilogue ----------------
    int gm = m0 + wm * 64;
    int gn = n0 + wn * 32;
    #pragma unroll
    for (int mi = 0; mi < 4; mi++) {
        #pragma unroll
        for (int half = 0; half < 2; half++) {
            int row = gm + mi * 16 + (lane >> 2) + half * 8;
            #pragma unroll
            for (int ni = 0; ni < 4; ni++) {
                int col = gn + ni * 8 + (lane & 3) * 2;
                float v0 = acc[mi][ni][half * 2 + 0];
                float v1 = acc[mi][ni][half * 2 + 1];
                if (bias) { v0 += bias[col]; v1 += bias[col + 1]; }
                size_t idx = (size_t)row * N + col;
                float2 o;
                if (EPI == 0) {
                    o = make_float2(v0, v1);
                } else if (EPI == 1) {
                    o.x = 0.5f * v0 * (1.0f + erff(v0 * 0.70710678118654752f));
                    o.y = 0.5f * v1 * (1.0f + erff(v1 * 0.70710678118654752f));
                } else {
                    float2 ot = *(const float2*)(other + idx);
                    float2 rs = *(const float2*)(resid + idx);
                    o.x = ot.x + rs.x / (1.0f + __expf(-v0));
                    o.y = ot.y + rs.y / (1.0f + __expf(-v1));
                }
                *(float2*)(Cp + idx) = o;
            }
        }
    }
}

// ---------------- Attention pass A: per-row softmax stats ----------------
__global__ void __launch_bounds__(256, 2)
attn_pa(const float* __restrict__ q, const float* __restrict__ k,
        float* __restrict__ Mb, float* __restrict__ Lb) {
    int ttile = blockIdx.x, bh = blockIdx.y;
    int b = bh >> 4, h = bh & 15;
    int t0 = ttile * 64;
    const float* qg = q + ((size_t)h * ROWS + (size_t)b * TT + t0) * HS;
    const float* kg = k + ((size_t)h * ROWS + (size_t)b * TT) * HS;
    __shared__ float qsT[64][68];
    __shared__ float ksT[64][68];
    __shared__ float redM[64][17];
    __shared__ float redL[64][17];
    int tid = threadIdx.x;
    int tx = tid & 15, ty = tid >> 4;

    #pragma unroll
    for (int i = 0; i < 4; i++) {
        int idx = tid + i * 256;          // float4 index
        int r = idx >> 4, c4 = idx & 15;
        float4 v = *(const float4*)(qg + (size_t)r * HS + c4 * 4);
        qsT[c4*4+0][r] = v.x; qsT[c4*4+1][r] = v.y;
        qsT[c4*4+2][r] = v.z; qsT[c4*4+3][r] = v.w;
    }
    float mP[4], lP[4];
    #pragma unroll
    for (int i = 0; i < 4; i++) { mP[i] = -INFINITY; lP[i] = 0.f; }

    for (int st = 0; st <= ttile; st++) {
        __syncthreads();
        #pragma unroll
        for (int i = 0; i < 4; i++) {
            int idx = tid + i * 256;
            int r = idx >> 4, c4 = idx & 15;
            float4 v = *(const float4*)(kg + (size_t)(st*64 + r) * HS + c4 * 4);
            ksT[c4*4+0][r] = v.x; ksT[c4*4+1][r] = v.y;
            ksT[c4*4+2][r] = v.z; ksT[c4*4+3][r] = v.w;
        }
        __syncthreads();
        float acc[4][4];
        #pragma unroll
        for (int i = 0; i < 4; i++)
            #pragma unroll
            for (int j = 0; j < 4; j++) acc[i][j] = 0.f;
        #pragma unroll 16
        for (int kk = 0; kk < 64; kk++) {
            float4 a  = *(float4*)&qsT[kk][ty*4];
            float4 bv = *(float4*)&ksT[kk][tx*4];
            float aa[4] = {a.x, a.y, a.z, a.w};
            float bbv[4] = {bv.x, bv.y, bv.z, bv.w};
            #pragma unroll
            for (int i = 0; i < 4; i++)
                #pragma unroll
                for (int j = 0; j < 4; j++)
                    acc[i][j] += aa[i] * bbv[j];
        }
        int srow = st * 64;
        #pragma unroll
        for (int i = 0; i < 4; i++) {
            int t = t0 + ty * 4 + i;
            #pragma unroll
            for (int j = 0; j < 4; j++) {
                int s = srow + tx * 4 + j;
                if (s <= t) {
                    float sc = acc[i][j] * 0.125f;
                    float mN = fmaxf(mP[i], sc);
                    lP[i] = lP[i] * __expf(mP[i] - mN) + __expf(sc - mN);
                    mP[i] = mN;
                }
            }
        }
    }
    #pragma unroll
    for (int i = 0; i < 4; i++) {
        redM[ty*4+i][tx] = mP[i];
        redL[ty*4+i][tx] = lP[i];
    }
    __syncthreads();
    if (tid < 64) {
        float m = -INFINITY;
        #pragma unroll
        for (int j = 0; j < 16; j++) m = fmaxf(m, redM[tid][j]);
        float l = 0.f;
        #pragma unroll
        for (int j = 0; j < 16; j++) l += redL[tid][j] * __expf(redM[tid][j] - m);
        size_t o = (size_t)bh * TT + t0 + tid;
        Mb[o] = m; Lb[o] = l;
    }
}

// ---------------- Attention pass B: wei + attn ----------------
// dynamic smem: qsT[64*68] + kpT[64*68] + vs[64*68]
__global__ void __launch_bounds__(256, 2)
attn_pb(const float* __restrict__ q, const float* __restrict__ k,
        const float* __restrict__ v,
        const float* __restrict__ Mb, const float* __restrict__ Lb,
        float* __restrict__ wei, float* __restrict__ attn) {
    extern __shared__ float smem[];
    float* qsT = smem;
    float* kpT = smem + 64 * 68;
    float* vs  = smem + 2 * 64 * 68;
#define QS(kk, r) qsT[(kk)*68 + (r)]
#define KP(a, b2) kpT[(a)*68 + (b2)]
#define VS(r, c)  vs[(r)*68 + (c)]
    int ttile = blockIdx.x, bh = blockIdx.y;
    int b = bh >> 4, h = bh & 15;
    int t0 = ttile * 64;
    const float* qg = q + ((size_t)h * ROWS + (size_t)b * TT + t0) * HS;
    const float* kg = k + ((size_t)h * ROWS + (size_t)b * TT) * HS;
    const float* vg = v + ((size_t)h * ROWS + (size_t)b * TT) * HS;
    float* weib = wei + ((size_t)bh * TT + t0) * TT;
    int tid = threadIdx.x;
    int tx = tid & 15, ty = tid >> 4;

    #pragma unroll
    for (int i = 0; i < 4; i++) {
        int idx = tid + i * 256;
        int r = idx >> 4, c4 = idx & 15;
        float4 vv = *(const float4*)(qg + (size_t)r * HS + c4 * 4);
        QS(c4*4+0, r) = vv.x; QS(c4*4+1, r) = vv.y;
        QS(c4*4+2, r) = vv.z; QS(c4*4+3, r) = vv.w;
    }
    float mrow[4], invl[4];
    #pragma unroll
    for (int i = 0; i < 4; i++) {
        size_t o = (size_t)bh * TT + t0 + ty * 4 + i;
        mrow[i] = Mb[o];
        invl[i] = 1.0f / Lb[o];
    }
    float oacc[4][4];
    #pragma unroll
    for (int i = 0; i < 4; i++)
        #pragma unroll
        for (int j = 0; j < 4; j++) oacc[i][j] = 0.f;

    for (int st = 0; st < NT; st++) {
        int sbase = st * 64;
        if (sbase > t0 + 63) {   // fully masked tile: zero-fill wei
            float4 z4 = make_float4(0.f, 0.f, 0.f, 0.f);
            #pragma unroll
            for (int i = 0; i < 4; i++)
                *(float4*)(weib + (size_t)(ty*4+i) * TT + sbase + tx*4) = z4;
            continue;
        }
        __syncthreads();
        #pragma unroll
        for (int i = 0; i < 4; i++) {
            int idx = tid + i * 256;
            int r = idx >> 4, c4 = idx & 15;
            float4 kv = *(const float4*)(kg + (size_t)(sbase + r) * HS + c4 * 4);
            KP(c4*4+0, r) = kv.x; KP(c4*4+1, r) = kv.y;
            KP(c4*4+2, r) = kv.z; KP(c4*4+3, r) = kv.w;
            float4 vv = *(const float4*)(vg + (size_t)(sbase + r) * HS + c4 * 4);
            *(float4*)&VS(r, c4*4) = vv;
        }
        __syncthreads();
        float acc[4][4];
        #pragma unroll
        for (int i = 0; i < 4; i++)
            #pragma unroll
            for (int j = 0; j < 4; j++) acc[i][j] = 0.f;
        #pragma unroll 16
        for (int kk = 0; kk < 64; kk++) {
            float4 a  = *(float4*)&QS(kk, ty*4);
            float4 bv = *(float4*)&KP(kk, tx*4);
            float aa[4] = {a.x, a.y, a.z, a.w};
            float bbv[4] = {bv.x, bv.y, bv.z, bv.w};
            #pragma unroll
            for (int i = 0; i < 4; i++)
                #pragma unroll
                for (int j = 0; j < 4; j++)
                    acc[i][j] += aa[i] * bbv[j];
        }
        float p[4][4];
        #pragma unroll
        for (int i = 0; i < 4; i++) {
            int t = t0 + ty * 4 + i;
            #pragma unroll
            for (int j = 0; j < 4; j++) {
                int s = sbase + tx * 4 + j;
                p[i][j] = (s <= t)
                    ? __expf(acc[i][j] * 0.125f - mrow[i]) * invl[i] : 0.f;
            }
            *(float4*)(weib + (size_t)(ty*4+i) * TT + sbase + tx*4) =
                make_float4(p[i][0], p[i][1], p[i][2], p[i][3]);
        }
        __syncthreads();   // everyone done reading kpT as K
        #pragma unroll
        for (int i = 0; i < 4; i++)
            *(float4*)&KP(ty*4+i, tx*4) =
                make_float4(p[i][0], p[i][1], p[i][2], p[i][3]);
        __syncthreads();
        #pragma unroll 8
        for (int j = 0; j < 64; j++) {
            float4 vv = *(float4*)&VS(j, tx*4);
            #pragma unroll
            for (int i = 0; i < 4; i++) {
                float pp = KP(ty*4+i, j);
                oacc[i][0] += pp * vv.x;
                oacc[i][1] += pp * vv.y;
                oacc[i][2] += pp * vv.z;
                oacc[i][3] += pp * vv.w;
            }
        }
    }
    size_t arow0 = (size_t)b * TT + t0;
    #pragma unroll
    for (int i = 0; i < 4; i++)
        *(float4*)(attn + (arow0 + ty*4 + i) * EE + h * HS + tx * 4) =
            make_float4(oacc[i][0], oacc[i][1], oacc[i][2], oacc[i][3]);
#undef QS
#undef KP
#undef VS
}

// ---------------- launch ----------------
extern "C" void kernel_launch(void* const* d_in, const int* in_sizes, int n_in,
                              void* d_out, int out_size) {
    const float* x      = (const float*)d_in[0];
    const float* wq     = (const float*)d_in[1];
    const float* wk     = (const float*)d_in[2];
    const float* wv     = (const float*)d_in[3];
    const float* wp     = (const float*)d_in[4];
    const float* bp     = (const float*)d_in[5];
    const float* ln1_g  = (const float*)d_in[6];
    const float* ln1_b  = (const float*)d_in[7];
    const float* ln2_g  = (const float*)d_in[8];
    const float* ln2_b  = (const float*)d_in[9];
    const float* w1     = (const float*)d_in[10];
    const float* b1     = (const float*)d_in[11];
    const float* w2     = (const float*)d_in[12];
    const float* b2     = (const float*)d_in[13];
    const float* w3     = (const float*)d_in[14];
    const float* b3     = (const float*)d_in[15];
    const float* wg_att = (const float*)d_in[16];
    const float* bg_att = (const float*)d_in[17];
    const float* wg_ff  = (const float*)d_in[18];
    const float* bg_ff  = (const float*)d_in[19];

    float* out_x   = (float*)d_out;                       // [B,T,E]
    float* out_wei = (float*)d_out + (size_t)ROWS * EE;   // [B,H,T,T]

    float *h1, *q, *k, *v, *attn, *sa, *x1, *h2, *f1, *f2, *f3, *Mb, *Lb;
    cudaGetSymbolAddress((void**)&h1, g_h1);
    cudaGetSymbolAddress((void**)&q,  g_q);
    cudaGetSymbolAddress((void**)&k,  g_k);
    cudaGetSymbolAddress((void**)&v,  g_v);
    cudaGetSymbolAddress((void**)&attn, g_attn);
    cudaGetSymbolAddress((void**)&sa, g_sa);
    cudaGetSymbolAddress((void**)&x1, g_x1);
    cudaGetSymbolAddress((void**)&h2, g_h2);
    cudaGetSymbolAddress((void**)&f1, g_f1);
    cudaGetSymbolAddress((void**)&f2, g_f2);
    cudaGetSymbolAddress((void**)&f3, g_f3);
    cudaGetSymbolAddress((void**)&Mb, g_M);
    cudaGetSymbolAddress((void**)&Lb, g_L);

    int pb_smem = 3 * 64 * 68 * 4;
    cudaFuncSetAttribute(attn_pb, cudaFuncAttributeMaxDynamicSharedMemorySize,
                         pb_smem);

    // 1) h1 = LN1(x)
    ln_kernel<<<ROWS, 256>>>(x, ln1_g, ln1_b, h1);

    // 2) fused q/k/v: z = 48 (3 weights x 16 heads), tf32 MMA + cp.async
    size_t wStrideZ = (size_t)EE * HS;       // per-head weight
    size_t cStrideZ = (size_t)ROWS * HS;     // per-head output
    mma_gemm<64,0,1><<<dim3(1, ROWS/BMM, 48), 128>>>(h1, wq, wk, wv,
        nullptr, q, k, v, ROWS, HS, EE, wStrideZ, cStrideZ, nullptr, nullptr);

    // 3) attention
    attn_pa<<<dim3(NT, BB*HH), 256>>>(q, k, Mb, Lb);
    attn_pb<<<dim3(NT, BB*HH), 256, pb_smem>>>(q, k, v, Mb, Lb, out_wei, attn);

    // 4) sa = attn @ wp + bp
    mma_gemm<128,0,0><<<dim3(EE/128, ROWS/BMM, 1), 256>>>(attn, wp,
        nullptr, nullptr, bp, sa, nullptr, nullptr,
        ROWS, EE, EE, 0, 0, nullptr, nullptr);

    // 5) x1 = sa + sigmoid(sa @ wg_att + bg_att) * x
    mma_gemm<128,2,0><<<dim3(EE/128, ROWS/BMM, 1), 256>>>(sa, wg_att,
        nullptr, nullptr, bg_att, x1, nullptr, nullptr,
        ROWS, EE, EE, 0, 0, sa, x);

    // 6) h2 = LN2(x1)
    ln_kernel<<<ROWS, 256>>>(x1, ln2_g, ln2_b, h2);

    // 7) f1 = gelu(h2 @ w1 + b1)      [4096 x 4096]
    mma_gemm<128,1,0><<<dim3(4*EE/128, ROWS/BMM, 1), 256>>>(h2, w1,
        nullptr, nullptr, b1, f1, nullptr, nullptr,
        ROWS, 4*EE, EE, 0, 0, nullptr, nullptr);

    // 8) f2 = gelu(f1 @ w2 + b2)      [4096 x 2048], K=4096
    mma_gemm<128,1,0><<<dim3(2*EE/128, ROWS/BMM, 1), 256>>>(f1, w2,
        nullptr, nullptr, b2, f2, nullptr, nullptr,
        ROWS, 2*EE, 4*EE, 0, 0, nullptr, nullptr);

    // 9) f3 = f2 @ w3 + b3            [4096 x 1024], K=2048
    mma_gemm<128,0,0><<<dim3(EE/128, ROWS/BMM, 1), 256>>>(f2, w3,
        nullptr, nullptr, b3, f3, nullptr, nullptr,
        ROWS, EE, 2*EE, 0, 0, nullptr, nullptr);

    // 10) out_x = f3 + sigmoid(f3 @ wg_ff + bg_ff) * x1   (K = E)
    mma_gemm<128,2,0><<<dim3(EE/128, ROWS/BMM, 1), 256>>>(f3, wg_ff,
        nullptr, nullptr, bg_ff, out_x, nullptr, nullptr,
        ROWS, EE, EE, 0, 0, f3, x1);
}

// round 10
// speedup vs baseline: 2.7791x; 1.3110x over previous
#include <cuda_runtime.h>
#include <cuda_bf16.h>
#include <math.h>

// Problem constants
#define BB   2
#define TT   2048
#define EE   1024
#define HH   16
#define HS   64
#define ROWS (BB*TT)          // 4096

// ---------------- device scratch ----------------
__device__ float g_h1[ROWS*EE];
__device__ float g_q [ROWS*EE];
__device__ float g_k [ROWS*EE];
__device__ float g_v [ROWS*EE];
__device__ float g_attn[ROWS*EE];
__device__ float g_sa [ROWS*EE];
__device__ float g_x1 [ROWS*EE];
__device__ float g_h2 [ROWS*EE];
__device__ float g_f1 [ROWS*4*EE];
__device__ float g_f2 [ROWS*2*EE];
__device__ float g_f3 [ROWS*EE];
__device__ float g_L  [BB*HH*TT];

// ---------------- LayerNorm ----------------
__global__ void ln_kernel(const float* __restrict__ x,
                          const float* __restrict__ g,
                          const float* __restrict__ b,
                          float* __restrict__ out) {
    int row = blockIdx.x;
    int tid = threadIdx.x;                 // 256 threads, 4 floats each
    const float* xr = x + (size_t)row * EE;
    float4 v = *(const float4*)(xr + tid * 4);
    float s  = v.x + v.y + v.z + v.w;
    float ss = v.x*v.x + v.y*v.y + v.z*v.z + v.w*v.w;
    __shared__ float sm[32], sm2[32];
    int lane = tid & 31, warp = tid >> 5;
    #pragma unroll
    for (int o = 16; o > 0; o >>= 1) {
        s  += __shfl_down_sync(0xffffffffu, s,  o);
        ss += __shfl_down_sync(0xffffffffu, ss, o);
    }
    if (lane == 0) { sm[warp] = s; sm2[warp] = ss; }
    __syncthreads();
    if (warp == 0) {
        float a = (lane < 8) ? sm[lane]  : 0.f;
        float c = (lane < 8) ? sm2[lane] : 0.f;
        #pragma unroll
        for (int o = 4; o > 0; o >>= 1) {
            a += __shfl_down_sync(0xffffffffu, a, o);
            c += __shfl_down_sync(0xffffffffu, c, o);
        }
        if (lane == 0) { sm[0] = a; sm2[0] = c; }
    }
    __syncthreads();
    float mu  = sm[0]  * (1.0f / EE);
    float var = sm2[0] * (1.0f / EE) - mu * mu;
    float rstd = rsqrtf(var + 1e-5f);
    float4 gg = *(const float4*)(g + tid * 4);
    float4 bb = *(const float4*)(b + tid * 4);
    float4 o;
    o.x = (v.x - mu) * rstd * gg.x + bb.x;
    o.y = (v.y - mu) * rstd * gg.y + bb.y;
    o.z = (v.z - mu) * rstd * gg.z + bb.z;
    o.w = (v.w - mu) * rstd * gg.w + bb.w;
    *(float4*)(out + (size_t)row * EE + tid * 4) = o;
}

// ---------------- tf32 / cp.async helpers ----------------
__device__ __forceinline__ unsigned f2tf32(float f) {
    unsigned u;
    asm("cvt.rna.tf32.f32 %0, %1;" : "=r"(u) : "f"(f));
    return u;
}

__device__ __forceinline__ void mma_tf32(float* c, const unsigned* a,
                                         const unsigned* b) {
    asm volatile(
        "mma.sync.aligned.m16n8k8.row.col.f32.tf32.tf32.f32 "
        "{%0,%1,%2,%3}, {%4,%5,%6,%7}, {%8,%9}, {%0,%1,%2,%3};"
        : "+f"(c[0]), "+f"(c[1]), "+f"(c[2]), "+f"(c[3])
        : "r"(a[0]), "r"(a[1]), "r"(a[2]), "r"(a[3]),
          "r"(b[0]), "r"(b[1]));
}

__device__ __forceinline__ void cp_async16(void* smem_dst, const void* gsrc) {
    unsigned s = (unsigned)__cvta_generic_to_shared(smem_dst);
    asm volatile("cp.async.cg.shared.global [%0], [%1], 16;"
                 :: "r"(s), "l"(gsrc));
}
#define CP_COMMIT() asm volatile("cp.async.commit_group;" ::: "memory")
#define CP_WAIT0()  asm volatile("cp.async.wait_group 0;" ::: "memory")

// ---------------- tf32 MMA GEMM, cp.async double-buffered ----------------
// (unchanged from the round-5 kernel that PASSED at 2443 us)
#define BMM 128
#define BKK 16

template<int BN, int EPI, int QKV>
__global__ void __launch_bounds__((BN == 128) ? 256 : 128, (BN == 128) ? 2 : 3)
mma_gemm(const float* __restrict__ A,
         const float* __restrict__ B0, const float* __restrict__ B1,
         const float* __restrict__ B2,
         const float* __restrict__ bias,
         float* __restrict__ C0, float* __restrict__ C1,
         float* __restrict__ C2,
         int M, int N, int K, size_t bStrideZ, size_t cStrideZ,
         const float* __restrict__ other, const float* __restrict__ resid) {
    constexpr int THREADS = (BN == 128) ? 256 : 128;
    constexpr int NWN = BN / 32;            // warps along N
    constexpr int AP  = 20;                 // A smem pitch (words)
    constexpr int BP  = BN + 8;             // B smem pitch (words)
    constexpr int LA  = 512 / THREADS;      // A float4 per thread per stage
    constexpr int LB  = (BKK * BN / 4) / THREADS;
    constexpr int BNQ = BN / 4;

    __shared__ float As[2][BMM * AP];
    __shared__ float Bs[2][BKK * BP];

    const float* Bp;
    float* Cp;
    if (QKV) {
        int zz = blockIdx.z;
        int which = zz >> 4, head = zz & 15;
        const float* Bsel = (which == 0) ? B0 : ((which == 1) ? B1 : B2);
        float*       Csel = (which == 0) ? C0 : ((which == 1) ? C1 : C2);
        Bp = Bsel + (size_t)head * bStrideZ;
        Cp = Csel + (size_t)head * cStrideZ;
    } else {
        Bp = B0; Cp = C0;
    }

    int m0 = blockIdx.y * BMM, n0 = blockIdx.x * BN;
    int tid  = threadIdx.x;
    int lane = tid & 31, warp = tid >> 5;
    int wm = warp / NWN, wn = warp % NWN;

    float acc[4][4][4];
    #pragma unroll
    for (int i = 0; i < 4; i++)
        #pragma unroll
        for (int j = 0; j < 4; j++)
            #pragma unroll
            for (int l = 0; l < 4; l++) acc[i][j][l] = 0.f;

    auto stage = [&](int s, int k0) {
        #pragma unroll
        for (int i = 0; i < LA; i++) {
            int idx = tid + i * THREADS;
            int r = idx >> 2, c4 = idx & 3;
            cp_async16(&As[s][r * AP + c4 * 4],
                       A + (size_t)(m0 + r) * K + k0 + c4 * 4);
        }
        #pragma unroll
        for (int i = 0; i < LB; i++) {
            int idx = tid + i * THREADS;
            int r = idx / BNQ, c4 = idx % BNQ;
            cp_async16(&Bs[s][r * BP + c4 * 4],
                       Bp + (size_t)(k0 + r) * N + n0 + c4 * 4);
        }
    };

    stage(0, 0);
    CP_COMMIT();

    int nk = K / BKK;
    for (int it = 0; it < nk; it++) {
        CP_WAIT0();
        __syncthreads();
        if (it + 1 < nk) {
            stage((it + 1) & 1, (it + 1) * BKK);
            CP_COMMIT();
        }
        int s = it & 1;
        #pragma unroll
        for (int ks = 0; ks < BKK; ks += 8) {
            int lk = ks + (lane & 3);
            int lm = lane >> 2;
            unsigned a[4][4], b[4][2];
            #pragma unroll
            for (int mi = 0; mi < 4; mi++) {
                int m = wm * 64 + mi * 16 + lm;
                a[mi][0] = f2tf32(As[s][m * AP + lk]);
                a[mi][1] = f2tf32(As[s][(m + 8) * AP + lk]);
                a[mi][2] = f2tf32(As[s][m * AP + lk + 4]);
                a[mi][3] = f2tf32(As[s][(m + 8) * AP + lk + 4]);
            }
            #pragma unroll
            for (int ni = 0; ni < 4; ni++) {
                int n = wn * 32 + ni * 8 + lm;
                b[ni][0] = f2tf32(Bs[s][lk * BP + n]);
                b[ni][1] = f2tf32(Bs[s][(lk + 4) * BP + n]);
            }
            #pragma unroll
            for (int mi = 0; mi < 4; mi++)
                #pragma unroll
                for (int ni = 0; ni < 4; ni++)
                    mma_tf32(acc[mi][ni], a[mi], b[ni]);
        }
    }

    // ---------------- epilogue ----------------
    int gm = m0 + wm * 64;
    int gn = n0 + wn * 32;
    #pragma unroll
    for (int mi = 0; mi < 4; mi++) {
        #pragma unroll
        for (int half = 0; half < 2; half++) {
            int row = gm + mi * 16 + (lane >> 2) + half * 8;
            #pragma unroll
            for (int ni = 0; ni < 4; ni++) {
                int col = gn + ni * 8 + (lane & 3) * 2;
                float v0 = acc[mi][ni][half * 2 + 0];
                float v1 = acc[mi][ni][half * 2 + 1];
                if (bias) { v0 += bias[col]; v1 += bias[col + 1]; }
                size_t idx = (size_t)row * N + col;
                float2 o;
                if (EPI == 0) {
                    o = make_float2(v0, v1);
                } else if (EPI == 1) {
                    o.x = 0.5f * v0 * (1.0f + erff(v0 * 0.70710678118654752f));
                    o.y = 0.5f * v1 * (1.0f + erff(v1 * 0.70710678118654752f));
                } else {
                    float2 ot = *(const float2*)(other + idx);
                    float2 rs = *(const float2*)(resid + idx);
                    o.x = ot.x + rs.x / (1.0f + __expf(-v0));
                    o.y = ot.y + rs.y / (1.0f + __expf(-v1));
                }
                *(float2*)(Cp + idx) = o;
            }
        }
    }
}

// ==================== MMA attention (de-risked, linear barriers) ========
// 8 warps (2M x 4N), warp tile 64x16, HS=64 contraction = 8 k8 steps.
// Softmax without max subtraction (scores O(1); softmax shift-invariant).
#define QP 68
#define KPP 68
#define VPP 72
#define PPP 68

__device__ __forceinline__ void s_tile_mma(const float* __restrict__ Qs,
                                           const float* __restrict__ Ks,
                                           int wm, int wn, int lane,
                                           float acc[4][2][4]) {
    #pragma unroll
    for (int mi = 0; mi < 4; mi++)
        #pragma unroll
        for (int ni = 0; ni < 2; ni++)
            #pragma unroll
            for (int l = 0; l < 4; l++) acc[mi][ni][l] = 0.f;
    int lm = lane >> 2, lk = lane & 3;
    #pragma unroll
    for (int ks = 0; ks < 8; ks++) {
        int kb = ks * 8;
        unsigned a[4][4], b[2][2];
        #pragma unroll
        for (int mi = 0; mi < 4; mi++) {
            int m = wm * 64 + mi * 16 + lm;
            a[mi][0] = f2tf32(Qs[m * QP + kb + lk]);
            a[mi][1] = f2tf32(Qs[(m + 8) * QP + kb + lk]);
            a[mi][2] = f2tf32(Qs[m * QP + kb + lk + 4]);
            a[mi][3] = f2tf32(Qs[(m + 8) * QP + kb + lk + 4]);
        }
        #pragma unroll
        for (int ni = 0; ni < 2; ni++) {
            int n = wn * 16 + ni * 8 + lm;
            b[ni][0] = f2tf32(Ks[n * KPP + kb + lk]);
            b[ni][1] = f2tf32(Ks[n * KPP + kb + lk + 4]);
        }
        #pragma unroll
        for (int mi = 0; mi < 4; mi++)
            #pragma unroll
            for (int ni = 0; ni < 2; ni++)
                mma_tf32(acc[mi][ni], a[mi], b[ni]);
    }
}

// ---- Pass A: l[t] = sum_{s<=t} exp(score) ----
__global__ void __launch_bounds__(256)
attn_sum(const float* __restrict__ q, const float* __restrict__ k,
         float* __restrict__ Lb) {
    extern __shared__ float sm[];
    float* Qs   = sm;                     // 128*68
    float* Ks   = sm + 128 * QP;          // 64*68
    float* Lred = Ks + 64 * KPP;          // 128*4

    int bh = blockIdx.y;
    int qt = (int)(gridDim.x - 1) - (int)blockIdx.x;
    int b = bh >> 4, h = bh & 15;
    int qbase = qt * 128;
    const float* qg = q + ((size_t)h * ROWS + (size_t)b * TT + qbase) * HS;
    const float* kg = k + ((size_t)h * ROWS + (size_t)b * TT) * HS;

    int tid = threadIdx.x;
    int lane = tid & 31, warp = tid >> 5;
    int wm = warp >> 2, wn = warp & 3;
    int lm = lane >> 2, lk = lane & 3;

    // load Q tile
    #pragma unroll
    for (int i = 0; i < 8; i++) {
        int idx = tid + i * 256;
        int r = idx >> 4, c4 = idx & 15;
        cp_async16(&Qs[r * QP + c4 * 4], qg + (size_t)r * HS + c4 * 4);
    }
    CP_COMMIT();
    CP_WAIT0();
    __syncthreads();

    float lsum[4][2];
    #pragma unroll
    for (int mi = 0; mi < 4; mi++) { lsum[mi][0] = 0.f; lsum[mi][1] = 0.f; }

    int nkt = 2 * qt + 2;
    for (int kt = 0; kt < nkt; kt++) {
        __syncthreads();                 // previous iter done with Ks
        #pragma unroll
        for (int i = 0; i < 4; i++) {
            int idx = tid + i * 256;
            int r = idx >> 4, c4 = idx & 15;
            cp_async16(&Ks[r * KPP + c4 * 4],
                       kg + (size_t)(kt * 64 + r) * HS + c4 * 4);
        }
        CP_COMMIT();
        CP_WAIT0();
        __syncthreads();

        float acc[4][2][4];
        s_tile_mma(Qs, Ks, wm, wn, lane, acc);
        #pragma unroll
        for (int mi = 0; mi < 4; mi++) {
            int rq = qbase + wm * 64 + mi * 16 + lm;
            #pragma unroll
            for (int ni = 0; ni < 2; ni++) {
                int kc = kt * 64 + wn * 16 + ni * 8 + 2 * lk;
                float* c = acc[mi][ni];
                if (kc     <= rq)     lsum[mi][0] += __expf(c[0] * 0.125f);
                if (kc + 1 <= rq)     lsum[mi][0] += __expf(c[1] * 0.125f);
                if (kc     <= rq + 8) lsum[mi][1] += __expf(c[2] * 0.125f);
                if (kc + 1 <= rq + 8) lsum[mi][1] += __expf(c[3] * 0.125f);
            }
        }
    }

    #pragma unroll
    for (int mi = 0; mi < 4; mi++)
        #pragma unroll
        for (int hf = 0; hf < 2; hf++) {
            float v = lsum[mi][hf];
            v += __shfl_xor_sync(0xffffffffu, v, 1);
            v += __shfl_xor_sync(0xffffffffu, v, 2);
            if (lk == 0)
                Lred[(wm * 64 + mi * 16 + lm + hf * 8) * 4 + wn] = v;
        }
    __syncthreads();
    if (tid < 128) {
        float l = Lred[tid * 4] + Lred[tid * 4 + 1] +
                  Lred[tid * 4 + 2] + Lred[tid * 4 + 3];
        Lb[(size_t)bh * TT + qbase + tid] = l;
    }
}

// ---- Pass B: wei + attn via MMA ----
__global__ void __launch_bounds__(256)
attn_out(const float* __restrict__ q, const float* __restrict__ k,
         const float* __restrict__ v, const float* __restrict__ Lb,
         float* __restrict__ wei, float* __restrict__ attn) {
    extern __shared__ float sm[];
    float* Qs = sm;                        // 128*68
    float* Ks = Qs + 128 * QP;             // 64*68
    float* Vs = Ks + 64 * KPP;             // 64*72
    float* Ps = Vs + 64 * VPP;             // 128*68

    int bh = blockIdx.y;
    int qt = (int)(gridDim.x - 1) - (int)blockIdx.x;
    int b = bh >> 4, h = bh & 15;
    int qbase = qt * 128;
    const float* qg = q + ((size_t)h * ROWS + (size_t)b * TT + qbase) * HS;
    const float* kg = k + ((size_t)h * ROWS + (size_t)b * TT) * HS;
    const float* vg = v + ((size_t)h * ROWS + (size_t)b * TT) * HS;
    float* weib = wei + ((size_t)bh * TT + qbase) * TT;

    int tid = threadIdx.x;
    int lane = tid & 31, warp = tid >> 5;
    int wm = warp >> 2, wn = warp & 3;
    int lm = lane >> 2, lk = lane & 3;

    // Q tile
    #pragma unroll
    for (int i = 0; i < 8; i++) {
        int idx = tid + i * 256;
        int r = idx >> 4, c4 = idx & 15;
        cp_async16(&Qs[r * QP + c4 * 4], qg + (size_t)r * HS + c4 * 4);
    }
    CP_COMMIT();

    float invl[4][2];
    #pragma unroll
    for (int mi = 0; mi < 4; mi++)
        #pragma unroll
        for (int hf = 0; hf < 2; hf++)
            invl[mi][hf] = 1.0f /
                Lb[(size_t)bh * TT + qbase + wm * 64 + mi * 16 + lm + hf * 8];

    float oacc[4][2][4];
    #pragma unroll
    for (int mi = 0; mi < 4; mi++)
        #pragma unroll
        for (int ni = 0; ni < 2; ni++)
            #pragma unroll
            for (int l = 0; l < 4; l++) oacc[mi][ni][l] = 0.f;

    CP_WAIT0();
    __syncthreads();

    int nkt = 2 * qt + 2;
    for (int kt = 0; kt < nkt; kt++) {
        __syncthreads();   // previous iter done with Ks/Vs/Ps
        // stage K and V together, single group
        #pragma unroll
        for (int i = 0; i < 4; i++) {
            int idx = tid + i * 256;
            int r = idx >> 4, c4 = idx & 15;
            cp_async16(&Ks[r * KPP + c4 * 4],
                       kg + (size_t)(kt * 64 + r) * HS + c4 * 4);
            cp_async16(&Vs[r * VPP + c4 * 4],
                       vg + (size_t)(kt * 64 + r) * HS + c4 * 4);
        }
        CP_COMMIT();
        CP_WAIT0();
        __syncthreads();

        float acc[4][2][4];
        s_tile_mma(Qs, Ks, wm, wn, lane, acc);

        // p = exp(s/8)/l with causal mask -> Ps
        #pragma unroll
        for (int mi = 0; mi < 4; mi++) {
            int r0 = wm * 64 + mi * 16 + lm;
            int rq0 = qbase + r0, rq1 = rq0 + 8;
            #pragma unroll
            for (int ni = 0; ni < 2; ni++) {
                int cl = wn * 16 + ni * 8 + 2 * lk;
                int kc = kt * 64 + cl;
                float* c = acc[mi][ni];
                float2 p0, p1;
                p0.x = (kc     <= rq0) ? __expf(c[0]*0.125f) * invl[mi][0] : 0.f;
                p0.y = (kc + 1 <= rq0) ? __expf(c[1]*0.125f) * invl[mi][0] : 0.f;
                p1.x = (kc     <= rq1) ? __expf(c[2]*0.125f) * invl[mi][1] : 0.f;
                p1.y = (kc + 1 <= rq1) ? __expf(c[3]*0.125f) * invl[mi][1] : 0.f;
                *(float2*)&Ps[r0 * PPP + cl] = p0;
                *(float2*)&Ps[(r0 + 8) * PPP + cl] = p1;
            }
        }
        __syncthreads();     // Ps complete

        // coalesced copy Ps -> wei
        #pragma unroll
        for (int i = 0; i < 8; i++) {
            int idx = tid + i * 256;
            int r = idx >> 4, c4 = idx & 15;
            *(float4*)(weib + (size_t)r * TT + kt * 64 + c4 * 4) =
                *(const float4*)&Ps[r * PPP + c4 * 4];
        }

        // O += P * V  (k = 64 keys)
        #pragma unroll
        for (int ks = 0; ks < 8; ks++) {
            int kb = ks * 8;
            unsigned a[4][4], bfr[2][2];
            #pragma unroll
            for (int mi = 0; mi < 4; mi++) {
                int m = wm * 64 + mi * 16 + lm;
                a[mi][0] = f2tf32(Ps[m * PPP + kb + lk]);
                a[mi][1] = f2tf32(Ps[(m + 8) * PPP + kb + lk]);
                a[mi][2] = f2tf32(Ps[m * PPP + kb + lk + 4]);
                a[mi][3] = f2tf32(Ps[(m + 8) * PPP + kb + lk + 4]);
            }
            #pragma unroll
            for (int ni = 0; ni < 2; ni++) {
                int n = wn * 16 + ni * 8 + lm;
                bfr[ni][0] = f2tf32(Vs[(kb + lk) * VPP + n]);
                bfr[ni][1] = f2tf32(Vs[(kb + lk + 4) * VPP + n]);
            }
            #pragma unroll
            for (int mi = 0; mi < 4; mi++)
                #pragma unroll
                for (int ni = 0; ni < 2; ni++)
                    mma_tf32(oacc[mi][ni], a[mi], bfr[ni]);
        }
    }

    // zero-fill wei tail (cols >= nkt*64)
    int kend4 = nkt * 16;   // in float4 units
    float4 z4 = make_float4(0.f, 0.f, 0.f, 0.f);
    for (int r = tid >> 4; r < 128; r += 16)
        for (int c4 = kend4 + (tid & 15); c4 < TT / 4; c4 += 16)
            *(float4*)(weib + (size_t)r * TT + c4 * 4) = z4;

    // write attn output [row][h*HS + col]
    float* attnb = attn + ((size_t)b * TT + qbase) * EE + h * HS;
    #pragma unroll
    for (int mi = 0; mi < 4; mi++) {
        int r0 = wm * 64 + mi * 16 + lm;
        #pragma unroll
        for (int ni = 0; ni < 2; ni++) {
            int col = wn * 16 + ni * 8 + 2 * lk;
            *(float2*)(attnb + (size_t)r0 * EE + col) =
                make_float2(oacc[mi][ni][0], oacc[mi][ni][1]);
            *(float2*)(attnb + (size_t)(r0 + 8) * EE + col) =
                make_float2(oacc[mi][ni][2], oacc[mi][ni][3]);
        }
    }
}

// ---------------- launch ----------------
extern "C" void kernel_launch(void* const* d_in, const int* in_sizes, int n_in,
                              void* d_out, int out_size) {
    const float* x      = (const float*)d_in[0];
    const float* wq     = (const float*)d_in[1];
    const float* wk     = (const float*)d_in[2];
    const float* wv     = (const float*)d_in[3];
    const float* wp     = (const float*)d_in[4];
    const float* bp     = (const float*)d_in[5];
    const float* ln1_g  = (const float*)d_in[6];
    const float* ln1_b  = (const float*)d_in[7];
    const float* ln2_g  = (const float*)d_in[8];
    const float* ln2_b  = (const float*)d_in[9];
    const float* w1     = (const float*)d_in[10];
    const float* b1     = (const float*)d_in[11];
    const float* w2     = (const float*)d_in[12];
    const float* b2     = (const float*)d_in[13];
    const float* w3     = (const float*)d_in[14];
    const float* b3     = (const float*)d_in[15];
    const float* wg_att = (const float*)d_in[16];
    const float* bg_att = (const float*)d_in[17];
    const float* wg_ff  = (const float*)d_in[18];
    const float* bg_ff  = (const float*)d_in[19];

    float* out_x   = (float*)d_out;                       // [B,T,E]
    float* out_wei = (float*)d_out + (size_t)ROWS * EE;   // [B,H,T,T]

    float *h1, *q, *k, *v, *attn, *sa, *x1, *h2, *f1, *f2, *f3, *Lb;
    cudaGetSymbolAddress((void**)&h1, g_h1);
    cudaGetSymbolAddress((void**)&q,  g_q);
    cudaGetSymbolAddress((void**)&k,  g_k);
    cudaGetSymbolAddress((void**)&v,  g_v);
    cudaGetSymbolAddress((void**)&attn, g_attn);
    cudaGetSymbolAddress((void**)&sa, g_sa);
    cudaGetSymbolAddress((void**)&x1, g_x1);
    cudaGetSymbolAddress((void**)&h2, g_h2);
    cudaGetSymbolAddress((void**)&f1, g_f1);
    cudaGetSymbolAddress((void**)&f2, g_f2);
    cudaGetSymbolAddress((void**)&f3, g_f3);
    cudaGetSymbolAddress((void**)&Lb, g_L);

    int smA = (128 * QP + 64 * KPP + 128 * 4) * 4;
    int smB = (128 * QP + 64 * KPP + 64 * VPP + 128 * PPP) * 4;
    cudaFuncSetAttribute(attn_sum, cudaFuncAttributeMaxDynamicSharedMemorySize,
                         smA);
    cudaFuncSetAttribute(attn_out, cudaFuncAttributeMaxDynamicSharedMemorySize,
                         smB);

    // 1) h1 = LN1(x)
    ln_kernel<<<ROWS, 256>>>(x, ln1_g, ln1_b, h1);

    // 2) fused q/k/v: z = 48 (3 weights x 16 heads)
    size_t wStrideZ = (size_t)EE * HS;
    size_t cStrideZ = (size_t)ROWS * HS;
    mma_gemm<64,0,1><<<dim3(1, ROWS/BMM, 48), 128>>>(h1, wq, wk, wv,
        nullptr, q, k, v, ROWS, HS, EE, wStrideZ, cStrideZ, nullptr, nullptr);

    // 3) attention (MMA, two-pass, no-max softmax)
    attn_sum<<<dim3(TT/128, BB*HH), 256, smA>>>(q, k, Lb);
    attn_out<<<dim3(TT/128, BB*HH), 256, smB>>>(q, k, v, Lb, out_wei, attn);

    // 4) sa = attn @ wp + bp
    mma_gemm<128,0,0><<<dim3(EE/128, ROWS/BMM, 1), 256>>>(attn, wp,
        nullptr, nullptr, bp, sa, nullptr, nullptr,
        ROWS, EE, EE, 0, 0, nullptr, nullptr);

    // 5) x1 = sa + sigmoid(sa @ wg_att + bg_att) * x
    mma_gemm<128,2,0><<<dim3(EE/128, ROWS/BMM, 1), 256>>>(sa, wg_att,
        nullptr, nullptr, bg_att, x1, nullptr, nullptr,
        ROWS, EE, EE, 0, 0, sa, x);

    // 6) h2 = LN2(x1)
    ln_kernel<<<ROWS, 256>>>(x1, ln2_g, ln2_b, h2);

    // 7) f1 = gelu(h2 @ w1 + b1)      [4096 x 4096]
    mma_gemm<128,1,0><<<dim3(4*EE/128, ROWS/BMM, 1), 256>>>(h2, w1,
        nullptr, nullptr, b1, f1, nullptr, nullptr,
        ROWS, 4*EE, EE, 0, 0, nullptr, nullptr);

    // 8) f2 = gelu(f1 @ w2 + b2)      [4096 x 2048], K=4096
    mma_gemm<128,1,0><<<dim3(2*EE/128, ROWS/BMM, 1), 256>>>(f1, w2,
        nullptr, nullptr, b2, f2, nullptr, nullptr,
        ROWS, 2*EE, 4*EE, 0, 0, nullptr, nullptr);

    // 9) f3 = f2 @ w3 + b3            [4096 x 1024], K=2048
    mma_gemm<128,0,0><<<dim3(EE/128, ROWS/BMM, 1), 256>>>(f2, w3,
        nullptr, nullptr, b3, f3, nullptr, nullptr,
        ROWS, EE, 2*EE, 0, 0, nullptr, nullptr);

    // 10) out_x = f3 + sigmoid(f3 @ wg_ff + bg_ff) * x1   (K = E)
    mma_gemm<128,2,0><<<dim3(EE/128, ROWS/BMM, 1), 256>>>(f3, wg_ff,
        nullptr, nullptr, bg_ff, out_x, nullptr, nullptr,
        ROWS, EE, EE, 0, 0, f3, x1);
}

// round 12
// speedup vs baseline: 2.8012x; 1.0080x over previous
#include <cuda_runtime.h>
#include <cuda_bf16.h>
#include <math.h>

// Problem constants
#define BB   2
#define TT   2048
#define EE   1024
#define HH   16
#define HS   64
#define ROWS (BB*TT)          // 4096

// ---------------- device scratch ----------------
__device__ float g_h1[ROWS*EE];
__device__ float g_q [ROWS*EE];
__device__ float g_k [ROWS*EE];
__device__ float g_v [ROWS*EE];
__device__ float g_attn[ROWS*EE];
__device__ float g_sa [ROWS*EE];
__device__ float g_x1 [ROWS*EE];
__device__ float g_h2 [ROWS*EE];
__device__ float g_f1 [ROWS*4*EE];
__device__ float g_f2 [ROWS*2*EE];
__device__ float g_f3 [ROWS*EE];
__device__ float g_L  [BB*HH*TT];

// ---------------- LayerNorm ----------------
__global__ void ln_kernel(const float* __restrict__ x,
                          const float* __restrict__ g,
                          const float* __restrict__ b,
                          float* __restrict__ out) {
    int row = blockIdx.x;
    int tid = threadIdx.x;                 // 256 threads, 4 floats each
    const float* xr = x + (size_t)row * EE;
    float4 v = *(const float4*)(xr + tid * 4);
    float s  = v.x + v.y + v.z + v.w;
    float ss = v.x*v.x + v.y*v.y + v.z*v.z + v.w*v.w;
    __shared__ float sm[32], sm2[32];
    int lane = tid & 31, warp = tid >> 5;
    #pragma unroll
    for (int o = 16; o > 0; o >>= 1) {
        s  += __shfl_down_sync(0xffffffffu, s,  o);
        ss += __shfl_down_sync(0xffffffffu, ss, o);
    }
    if (lane == 0) { sm[warp] = s; sm2[warp] = ss; }
    __syncthreads();
    if (warp == 0) {
        float a = (lane < 8) ? sm[lane]  : 0.f;
        float c = (lane < 8) ? sm2[lane] : 0.f;
        #pragma unroll
        for (int o = 4; o > 0; o >>= 1) {
            a += __shfl_down_sync(0xffffffffu, a, o);
            c += __shfl_down_sync(0xffffffffu, c, o);
        }
        if (lane == 0) { sm[0] = a; sm2[0] = c; }
    }
    __syncthreads();
    float mu  = sm[0]  * (1.0f / EE);
    float var = sm2[0] * (1.0f / EE) - mu * mu;
    float rstd = rsqrtf(var + 1e-5f);
    float4 gg = *(const float4*)(g + tid * 4);
    float4 bb = *(const float4*)(b + tid * 4);
    float4 o;
    o.x = (v.x - mu) * rstd * gg.x + bb.x;
    o.y = (v.y - mu) * rstd * gg.y + bb.y;
    o.z = (v.z - mu) * rstd * gg.z + bb.z;
    o.w = (v.w - mu) * rstd * gg.w + bb.w;
    *(float4*)(out + (size_t)row * EE + tid * 4) = o;
}

// ---------------- tf32 / cp.async helpers ----------------
__device__ __forceinline__ unsigned f2tf32(float f) {
    unsigned u;
    asm("cvt.rna.tf32.f32 %0, %1;" : "=r"(u) : "f"(f));
    return u;
}

__device__ __forceinline__ void mma_tf32(float* c, const unsigned* a,
                                         const unsigned* b) {
    asm volatile(
        "mma.sync.aligned.m16n8k8.row.col.f32.tf32.tf32.f32 "
        "{%0,%1,%2,%3}, {%4,%5,%6,%7}, {%8,%9}, {%0,%1,%2,%3};"
        : "+f"(c[0]), "+f"(c[1]), "+f"(c[2]), "+f"(c[3])
        : "r"(a[0]), "r"(a[1]), "r"(a[2]), "r"(a[3]),
          "r"(b[0]), "r"(b[1]));
}

__device__ __forceinline__ void cp_async16(void* smem_dst, const void* gsrc) {
    unsigned s = (unsigned)__cvta_generic_to_shared(smem_dst);
    asm volatile("cp.async.cg.shared.global [%0], [%1], 16;"
                 :: "r"(s), "l"(gsrc));
}
#define CP_COMMIT() asm volatile("cp.async.commit_group;" ::: "memory")
#define CP_WAIT0()  asm volatile("cp.async.wait_group 0;" ::: "memory")
#define CP_WAIT1()  asm volatile("cp.async.wait_group 1;" ::: "memory")

// ---------------- tf32 MMA GEMM, 3-stage cp.async pipeline ----------------
// Group-ordering invariant: prologue commits tiles 0,1; every loop iteration
// commits exactly one group (tile it+2, or EMPTY past the end). At the top of
// iteration it, groups 0..it+1 exist; wait_group 1 leaves at most group it+1
// pending, and groups complete in order, so tile it is guaranteed landed.
#define BMM 128
#define BKK 16
#define STG 3

template<int BN, int EPI, int QKV>
__global__ void __launch_bounds__((BN == 128) ? 256 : 128, (BN == 128) ? 2 : 3)
mma_gemm(const float* __restrict__ A,
         const float* __restrict__ B0, const float* __restrict__ B1,
         const float* __restrict__ B2,
         const float* __restrict__ bias,
         float* __restrict__ C0, float* __restrict__ C1,
         float* __restrict__ C2,
         int M, int N, int K, size_t bStrideZ, size_t cStrideZ,
         const float* __restrict__ other, const float* __restrict__ resid) {
    constexpr int THREADS = (BN == 128) ? 256 : 128;
    constexpr int NWN = BN / 32;            // warps along N
    constexpr int AP  = 20;                 // A smem pitch (words)
    constexpr int BP  = BN + 8;             // B smem pitch (words)
    constexpr int ASZ = BMM * AP;           // words per A stage
    constexpr int BSZ = BKK * BP;           // words per B stage
    constexpr int LA  = 512 / THREADS;      // A float4 per thread per stage
    constexpr int LB  = (BKK * BN / 4) / THREADS;
    constexpr int BNQ = BN / 4;

    extern __shared__ float dynsm[];
    float* As = dynsm;                      // [STG][ASZ]
    float* Bs = dynsm + STG * ASZ;          // [STG][BSZ]

    const float* Bp;
    float* Cp;
    if (QKV) {
        int zz = blockIdx.z;
        int which = zz >> 4, head = zz & 15;
        const float* Bsel = (which == 0) ? B0 : ((which == 1) ? B1 : B2);
        float*       Csel = (which == 0) ? C0 : ((which == 1) ? C1 : C2);
        Bp = Bsel + (size_t)head * bStrideZ;
        Cp = Csel + (size_t)head * cStrideZ;
    } else {
        Bp = B0; Cp = C0;
    }

    int m0 = blockIdx.y * BMM, n0 = blockIdx.x * BN;
    int tid  = threadIdx.x;
    int lane = tid & 31, warp = tid >> 5;
    int wm = warp / NWN, wn = warp % NWN;

    float acc[4][4][4];
    #pragma unroll
    for (int i = 0; i < 4; i++)
        #pragma unroll
        for (int j = 0; j < 4; j++)
            #pragma unroll
            for (int l = 0; l < 4; l++) acc[i][j][l] = 0.f;

    auto stage = [&](int s, int k0) {
        #pragma unroll
        for (int i = 0; i < LA; i++) {
            int idx = tid + i * THREADS;
            int r = idx >> 2, c4 = idx & 3;
            cp_async16(&As[s * ASZ + r * AP + c4 * 4],
                       A + (size_t)(m0 + r) * K + k0 + c4 * 4);
        }
        #pragma unroll
        for (int i = 0; i < LB; i++) {
            int idx = tid + i * THREADS;
            int r = idx / BNQ, c4 = idx % BNQ;
            cp_async16(&Bs[s * BSZ + r * BP + c4 * 4],
                       Bp + (size_t)(k0 + r) * N + n0 + c4 * 4);
        }
    };

    int nk = K / BKK;                       // >= 64 for all our shapes
    stage(0, 0);
    CP_COMMIT();                            // group: tile 0
    stage(1, BKK);
    CP_COMMIT();                            // group: tile 1

    for (int it = 0; it < nk; it++) {
        CP_WAIT1();                         // tile it landed
        __syncthreads();
        if (it + 2 < nk) stage((it + 2) % STG, (it + 2) * BKK);
        CP_COMMIT();                        // one group per iter (may be empty)

        const float* Asb = As + (it % STG) * ASZ;
        const float* Bsb = Bs + (it % STG) * BSZ;
        #pragma unroll
        for (int ks = 0; ks < BKK; ks += 8) {
            int lk = ks + (lane & 3);
            int lm = lane >> 2;
            unsigned a[4][4], b[4][2];
            #pragma unroll
            for (int mi = 0; mi < 4; mi++) {
                int m = wm * 64 + mi * 16 + lm;
                a[mi][0] = f2tf32(Asb[m * AP + lk]);
                a[mi][1] = f2tf32(Asb[(m + 8) * AP + lk]);
                a[mi][2] = f2tf32(Asb[m * AP + lk + 4]);
                a[mi][3] = f2tf32(Asb[(m + 8) * AP + lk + 4]);
            }
            #pragma unroll
            for (int ni = 0; ni < 4; ni++) {
                int n = wn * 32 + ni * 8 + lm;
                b[ni][0] = f2tf32(Bsb[lk * BP + n]);
                b[ni][1] = f2tf32(Bsb[(lk + 4) * BP + n]);
            }
            #pragma unroll
            for (int mi = 0; mi < 4; mi++)
                #pragma unroll
                for (int ni = 0; ni < 4; ni++)
                    mma_tf32(acc[mi][ni], a[mi], b[ni]);
        }
    }

    // ---------------- epilogue ----------------
    int gm = m0 + wm * 64;
    int gn = n0 + wn * 32;
    #pragma unroll
    for (int mi = 0; mi < 4; mi++) {
        #pragma unroll
        for (int half = 0; half < 2; half++) {
            int row = gm + mi * 16 + (lane >> 2) + half * 8;
            #pragma unroll
            for (int ni = 0; ni < 4; ni++) {
                int col = gn + ni * 8 + (lane & 3) * 2;
                float v0 = acc[mi][ni][half * 2 + 0];
                float v1 = acc[mi][ni][half * 2 + 1];
                if (bias) { v0 += bias[col]; v1 += bias[col + 1]; }
                size_t idx = (size_t)row * N + col;
                float2 o;
                if (EPI == 0) {
                    o = make_float2(v0, v1);
                } else if (EPI == 1) {
                    o.x = 0.5f * v0 * (1.0f + erff(v0 * 0.70710678118654752f));
                    o.y = 0.5f * v1 * (1.0f + erff(v1 * 0.70710678118654752f));
                } else {
                    float2 ot = *(const float2*)(other + idx);
                    float2 rs = *(const float2*)(resid + idx);
                    o.x = ot.x + rs.x / (1.0f + __expf(-v0));
                    o.y = ot.y + rs.y / (1.0f + __expf(-v1));
                }
                *(float2*)(Cp + idx) = o;
            }
        }
    }
}

// ==================== MMA attention ====================
// 8 warps (2M x 4N), warp tile 64x16, HS=64 contraction = 8 k8 steps.
// Softmax without max subtraction (scores O(1); softmax shift-invariant).
// Causal structure: for query tile qt (rows 128qt..128qt+127), key tiles
// kt <= 2qt-1 are FULLY unmasked; only kt = 2qt, 2qt+1 touch the diagonal.
#define QP 68
#define KPP 68
#define VPP 72
#define PPP 68

__device__ __forceinline__ void s_tile_mma(const float* __restrict__ Qs,
                                           const float* __restrict__ Ks,
                                           int wm, int wn, int lane,
                                           float acc[4][2][4]) {
    #pragma unroll
    for (int mi = 0; mi < 4; mi++)
        #pragma unroll
        for (int ni = 0; ni < 2; ni++)
            #pragma unroll
            for (int l = 0; l < 4; l++) acc[mi][ni][l] = 0.f;
    int lm = lane >> 2, lk = lane & 3;
    #pragma unroll
    for (int ks = 0; ks < 8; ks++) {
        int kb = ks * 8;
        unsigned a[4][4], b[2][2];
        #pragma unroll
        for (int mi = 0; mi < 4; mi++) {
            int m = wm * 64 + mi * 16 + lm;
            a[mi][0] = f2tf32(Qs[m * QP + kb + lk]);
            a[mi][1] = f2tf32(Qs[(m + 8) * QP + kb + lk]);
            a[mi][2] = f2tf32(Qs[m * QP + kb + lk + 4]);
            a[mi][3] = f2tf32(Qs[(m + 8) * QP + kb + lk + 4]);
        }
        #pragma unroll
        for (int ni = 0; ni < 2; ni++) {
            int n = wn * 16 + ni * 8 + lm;
            b[ni][0] = f2tf32(Ks[n * KPP + kb + lk]);
            b[ni][1] = f2tf32(Ks[n * KPP + kb + lk + 4]);
        }
        #pragma unroll
        for (int mi = 0; mi < 4; mi++)
            #pragma unroll
            for (int ni = 0; ni < 2; ni++)
                mma_tf32(acc[mi][ni], a[mi], b[ni]);
    }
}

// ---- Pass A: l[t] = sum_{s<=t} exp(score) ----
__global__ void __launch_bounds__(256)
attn_sum(const float* __restrict__ q, const float* __restrict__ k,
         float* __restrict__ Lb) {
    extern __shared__ float sm[];
    float* Qs   = sm;                     // 128*68
    float* Ks   = sm + 128 * QP;          // 64*68
    float* Lred = Ks + 64 * KPP;          // 128*4

    int bh = blockIdx.y;
    int qt = (int)(gridDim.x - 1) - (int)blockIdx.x;
    int b = bh >> 4, h = bh & 15;
    int qbase = qt * 128;
    const float* qg = q + ((size_t)h * ROWS + (size_t)b * TT + qbase) * HS;
    const float* kg = k + ((size_t)h * ROWS + (size_t)b * TT) * HS;

    int tid = threadIdx.x;
    int lane = tid & 31, warp = tid >> 5;
    int wm = warp >> 2, wn = warp & 3;
    int lm = lane >> 2, lk = lane & 3;

    // load Q tile
    #pragma unroll
    for (int i = 0; i < 8; i++) {
        int idx = tid + i * 256;
        int r = idx >> 4, c4 = idx & 15;
        cp_async16(&Qs[r * QP + c4 * 4], qg + (size_t)r * HS + c4 * 4);
    }
    CP_COMMIT();
    CP_WAIT0();
    __syncthreads();

    float lsum[4][2];
    #pragma unroll
    for (int mi = 0; mi < 4; mi++) { lsum[mi][0] = 0.f; lsum[mi][1] = 0.f; }

    int nkt = 2 * qt + 2;
    for (int kt = 0; kt < nkt; kt++) {
        __syncthreads();                 // previous iter done with Ks
        #pragma unroll
        for (int i = 0; i < 4; i++) {
            int idx = tid + i * 256;
            int r = idx >> 4, c4 = idx & 15;
            cp_async16(&Ks[r * KPP + c4 * 4],
                       kg + (size_t)(kt * 64 + r) * HS + c4 * 4);
        }
        CP_COMMIT();
        CP_WAIT0();
        __syncthreads();

        float acc[4][2][4];
        s_tile_mma(Qs, Ks, wm, wn, lane, acc);
        if (kt < 2 * qt) {               // fully unmasked fast path
            #pragma unroll
            for (int mi = 0; mi < 4; mi++)
                #pragma unroll
                for (int ni = 0; ni < 2; ni++) {
                    float* c = acc[mi][ni];
                    lsum[mi][0] += __expf(c[0] * 0.125f)
                                 + __expf(c[1] * 0.125f);
                    lsum[mi][1] += __expf(c[2] * 0.125f)
                                 + __expf(c[3] * 0.125f);
                }
        } else {                         // diagonal tiles: mask
            #pragma unroll
            for (int mi = 0; mi < 4; mi++) {
                int rq = qbase + wm * 64 + mi * 16 + lm;
                #pragma unroll
                for (int ni = 0; ni < 2; ni++) {
                    int kc = kt * 64 + wn * 16 + ni * 8 + 2 * lk;
                    float* c = acc[mi][ni];
                    if (kc     <= rq)     lsum[mi][0] += __expf(c[0] * 0.125f);
                    if (kc + 1 <= rq)     lsum[mi][0] += __expf(c[1] * 0.125f);
                    if (kc     <= rq + 8) lsum[mi][1] += __expf(c[2] * 0.125f);
                    if (kc + 1 <= rq + 8) lsum[mi][1] += __expf(c[3] * 0.125f);
                }
            }
        }
    }

    #pragma unroll
    for (int mi = 0; mi < 4; mi++)
        #pragma unroll
        for (int hf = 0; hf < 2; hf++) {
            float v = lsum[mi][hf];
            v += __shfl_xor_sync(0xffffffffu, v, 1);
            v += __shfl_xor_sync(0xffffffffu, v, 2);
            if (lk == 0)
                Lred[(wm * 64 + mi * 16 + lm + hf * 8) * 4 + wn] = v;
        }
    __syncthreads();
    if (tid < 128) {
        float l = Lred[tid * 4] + Lred[tid * 4 + 1] +
                  Lred[tid * 4 + 2] + Lred[tid * 4 + 3];
        Lb[(size_t)bh * TT + qbase + tid] = l;
    }
}

// ---- Pass B: wei + attn via MMA ----
__global__ void __launch_bounds__(256)
attn_out(const float* __restrict__ q, const float* __restrict__ k,
         const float* __restrict__ v, const float* __restrict__ Lb,
         float* __restrict__ wei, float* __restrict__ attn) {
    extern __shared__ float sm[];
    float* Qs = sm;                        // 128*68
    float* Ks = Qs + 128 * QP;             // 64*68
    float* Vs = Ks + 64 * KPP;             // 64*72
    float* Ps = Vs + 64 * VPP;             // 128*68

    int bh = blockIdx.y;
    int qt = (int)(gridDim.x - 1) - (int)blockIdx.x;
    int b = bh >> 4, h = bh & 15;
    int qbase = qt * 128;
    const float* qg = q + ((size_t)h * ROWS + (size_t)b * TT + qbase) * HS;
    const float* kg = k + ((size_t)h * ROWS + (size_t)b * TT) * HS;
    const float* vg = v + ((size_t)h * ROWS + (size_t)b * TT) * HS;
    float* weib = wei + ((size_t)bh * TT + qbase) * TT;

    int tid = threadIdx.x;
    int lane = tid & 31, warp = tid >> 5;
    int wm = warp >> 2, wn = warp & 3;
    int lm = lane >> 2, lk = lane & 3;

    // Q tile
    #pragma unroll
    for (int i = 0; i < 8; i++) {
        int idx = tid + i * 256;
        int r = idx >> 4, c4 = idx & 15;
        cp_async16(&Qs[r * QP + c4 * 4], qg + (size_t)r * HS + c4 * 4);
    }
    CP_COMMIT();

    float invl[4][2];
    #pragma unroll
    for (int mi = 0; mi < 4; mi++)
        #pragma unroll
        for (int hf = 0; hf < 2; hf++)
            invl[mi][hf] = 1.0f /
                Lb[(size_t)bh * TT + qbase + wm * 64 + mi * 16 + lm + hf * 8];

    float oacc[4][2][4];
    #pragma unroll
    for (int mi = 0; mi < 4; mi++)
        #pragma unroll
        for (int ni = 0; ni < 2; ni++)
            #pragma unroll
            for (int l = 0; l < 4; l++) oacc[mi][ni][l] = 0.f;

    CP_WAIT0();
    __syncthreads();

    int nkt = 2 * qt + 2;
    for (int kt = 0; kt < nkt; kt++) {
        __syncthreads();   // previous iter done with Ks/Vs/Ps
        // stage K and V together, single group
        #pragma unroll
        for (int i = 0; i < 4; i++) {
            int idx = tid + i * 256;
            int r = idx >> 4, c4 = idx & 15;
            cp_async16(&Ks[r * KPP + c4 * 4],
                       kg + (size_t)(kt * 64 + r) * HS + c4 * 4);
            cp_async16(&Vs[r * VPP + c4 * 4],
                       vg + (size_t)(kt * 64 + r) * HS + c4 * 4);
        }
        CP_COMMIT();
        CP_WAIT0();
        __syncthreads();

        float acc[4][2][4];
        s_tile_mma(Qs, Ks, wm, wn, lane, acc);

        // p = exp(s/8)/l -> Ps (mask only on the two diagonal tiles)
        if (kt < 2 * qt) {
            #pragma unroll
            for (int mi = 0; mi < 4; mi++) {
                int r0 = wm * 64 + mi * 16 + lm;
                #pragma unroll
                for (int ni = 0; ni < 2; ni++) {
                    int cl = wn * 16 + ni * 8 + 2 * lk;
                    float* c = acc[mi][ni];
                    float2 p0, p1;
                    p0.x = __expf(c[0] * 0.125f) * invl[mi][0];
                    p0.y = __expf(c[1] * 0.125f) * invl[mi][0];
                    p1.x = __expf(c[2] * 0.125f) * invl[mi][1];
                    p1.y = __expf(c[3] * 0.125f) * invl[mi][1];
                    *(float2*)&Ps[r0 * PPP + cl] = p0;
                    *(float2*)&Ps[(r0 + 8) * PPP + cl] = p1;
                }
            }
        } else {
            #pragma unroll
            for (int mi = 0; mi < 4; mi++) {
                int r0 = wm * 64 + mi * 16 + lm;
                int rq0 = qbase + r0, rq1 = rq0 + 8;
                #pragma unroll
                for (int ni = 0; ni < 2; ni++) {
                    int cl = wn * 16 + ni * 8 + 2 * lk;
                    int kc = kt * 64 + cl;
                    float* c = acc[mi][ni];
                    float2 p0, p1;
                    p0.x = (kc     <= rq0) ? __expf(c[0]*0.125f)*invl[mi][0] : 0.f;
                    p0.y = (kc + 1 <= rq0) ? __expf(c[1]*0.125f)*invl[mi][0] : 0.f;
                    p1.x = (kc     <= rq1) ? __expf(c[2]*0.125f)*invl[mi][1] : 0.f;
                    p1.y = (kc + 1 <= rq1) ? __expf(c[3]*0.125f)*invl[mi][1] : 0.f;
                    *(float2*)&Ps[r0 * PPP + cl] = p0;
                    *(float2*)&Ps[(r0 + 8) * PPP + cl] = p1;
                }
            }
        }
        __syncthreads();     // Ps complete

        // coalesced copy Ps -> wei
        #pragma unroll
        for (int i = 0; i < 8; i++) {
            int idx = tid + i * 256;
            int r = idx >> 4, c4 = idx & 15;
            *(float4*)(weib + (size_t)r * TT + kt * 64 + c4 * 4) =
                *(const float4*)&Ps[r * PPP + c4 * 4];
        }

        // O += P * V  (k = 64 keys)
        #pragma unroll
        for (int ks = 0; ks < 8; ks++) {
            int kb = ks * 8;
            unsigned a[4][4], bfr[2][2];
            #pragma unroll
            for (int mi = 0; mi < 4; mi++) {
                int m = wm * 64 + mi * 16 + lm;
                a[mi][0] = f2tf32(Ps[m * PPP + kb + lk]);
                a[mi][1] = f2tf32(Ps[(m + 8) * PPP + kb + lk]);
                a[mi][2] = f2tf32(Ps[m * PPP + kb + lk + 4]);
                a[mi][3] = f2tf32(Ps[(m + 8) * PPP + kb + lk + 4]);
            }
            #pragma unroll
            for (int ni = 0; ni < 2; ni++) {
                int n = wn * 16 + ni * 8 + lm;
                bfr[ni][0] = f2tf32(Vs[(kb + lk) * VPP + n]);
                bfr[ni][1] = f2tf32(Vs[(kb + lk + 4) * VPP + n]);
            }
            #pragma unroll
            for (int mi = 0; mi < 4; mi++)
                #pragma unroll
                for (int ni = 0; ni < 2; ni++)
                    mma_tf32(oacc[mi][ni], a[mi], bfr[ni]);
        }
    }

    // zero-fill wei tail (cols >= nkt*64)
    int kend4 = nkt * 16;   // in float4 units
    float4 z4 = make_float4(0.f, 0.f, 0.f, 0.f);
    for (int r = tid >> 4; r < 128; r += 16)
        for (int c4 = kend4 + (tid & 15); c4 < TT / 4; c4 += 16)
            *(float4*)(weib + (size_t)r * TT + c4 * 4) = z4;

    // write attn output [row][h*HS + col]
    float* attnb = attn + ((size_t)b * TT + qbase) * EE + h * HS;
    #pragma unroll
    for (int mi = 0; mi < 4; mi++) {
        int r0 = wm * 64 + mi * 16 + lm;
        #pragma unroll
        for (int ni = 0; ni < 2; ni++) {
            int col = wn * 16 + ni * 8 + 2 * lk;
            *(float2*)(attnb + (size_t)r0 * EE + col) =
                make_float2(oacc[mi][ni][0], oacc[mi][ni][1]);
            *(float2*)(attnb + (size_t)(r0 + 8) * EE + col) =
                make_float2(oacc[mi][ni][2], oacc[mi][ni][3]);
        }
    }
}

// ---------------- launch ----------------
extern "C" void kernel_launch(void* const* d_in, const int* in_sizes, int n_in,
                              void* d_out, int out_size) {
    const float* x      = (const float*)d_in[0];
    const float* wq     = (const float*)d_in[1];
    const float* wk     = (const float*)d_in[2];
    const float* wv     = (const float*)d_in[3];
    const float* wp     = (const float*)d_in[4];
    const float* bp     = (const float*)d_in[5];
    const float* ln1_g  = (const float*)d_in[6];
    const float* ln1_b  = (const float*)d_in[7];
    const float* ln2_g  = (const float*)d_in[8];
    const float* ln2_b  = (const float*)d_in[9];
    const float* w1     = (const float*)d_in[10];
    const float* b1     = (const float*)d_in[11];
    const float* w2     = (const float*)d_in[12];
    const float* b2     = (const float*)d_in[13];
    const float* w3     = (const float*)d_in[14];
    const float* b3     = (const float*)d_in[15];
    const float* wg_att = (const float*)d_in[16];
    const float* bg_att = (const float*)d_in[17];
    const float* wg_ff  = (const float*)d_in[18];
    const float* bg_ff  = (const float*)d_in[19];

    float* out_x   = (float*)d_out;                       // [B,T,E]
    float* out_wei = (float*)d_out + (size_t)ROWS * EE;   // [B,H,T,T]

    float *h1, *q, *k, *v, *attn, *sa, *x1, *h2, *f1, *f2, *f3, *Lb;
    cudaGetSymbolAddress((void**)&h1, g_h1);
    cudaGetSymbolAddress((void**)&q,  g_q);
    cudaGetSymbolAddress((void**)&k,  g_k);
    cudaGetSymbolAddress((void**)&v,  g_v);
    cudaGetSymbolAddress((void**)&attn, g_attn);
    cudaGetSymbolAddress((void**)&sa, g_sa);
    cudaGetSymbolAddress((void**)&x1, g_x1);
    cudaGetSymbolAddress((void**)&h2, g_h2);
    cudaGetSymbolAddress((void**)&f1, g_f1);
    cudaGetSymbolAddress((void**)&f2, g_f2);
    cudaGetSymbolAddress((void**)&f3, g_f3);
    cudaGetSymbolAddress((void**)&Lb, g_L);

    // dynamic smem sizes
    int smG64  = STG * (BMM * 20 + BKK * (64 + 8)) * 4;    // 44544
    int smG128 = STG * (BMM * 20 + BKK * (128 + 8)) * 4;   // 56832
    int smA = (128 * QP + 64 * KPP + 128 * 4) * 4;
    int smB = (128 * QP + 64 * KPP + 64 * VPP + 128 * PPP) * 4;
    cudaFuncSetAttribute(mma_gemm<64,0,1>,
        cudaFuncAttributeMaxDynamicSharedMemorySize, smG64);
    cudaFuncSetAttribute(mma_gemm<128,0,0>,
        cudaFuncAttributeMaxDynamicSharedMemorySize, smG128);
    cudaFuncSetAttribute(mma_gemm<128,1,0>,
        cudaFuncAttributeMaxDynamicSharedMemorySize, smG128);
    cudaFuncSetAttribute(mma_gemm<128,2,0>,
        cudaFuncAttributeMaxDynamicSharedMemorySize, smG128);
    cudaFuncSetAttribute(attn_sum,
        cudaFuncAttributeMaxDynamicSharedMemorySize, smA);
    cudaFuncSetAttribute(attn_out,
        cudaFuncAttributeMaxDynamicSharedMemorySize, smB);

    // 1) h1 = LN1(x)
    ln_kernel<<<ROWS, 256>>>(x, ln1_g, ln1_b, h1);

    // 2) fused q/k/v: z = 48 (3 weights x 16 heads)
    size_t wStrideZ = (size_t)EE * HS;
    size_t cStrideZ = (size_t)ROWS * HS;
    mma_gemm<64,0,1><<<dim3(1, ROWS/BMM, 48), 128, smG64>>>(h1, wq, wk, wv,
        nullptr, q, k, v, ROWS, HS, EE, wStrideZ, cStrideZ, nullptr, nullptr);

    // 3) attention (MMA, two-pass, no-max softmax)
    attn_sum<<<dim3(TT/128, BB*HH), 256, smA>>>(q, k, Lb);
    attn_out<<<dim3(TT/128, BB*HH), 256, smB>>>(q, k, v, Lb, out_wei, attn);

    // 4) sa = attn @ wp + bp
    mma_gemm<128,0,0><<<dim3(EE/128, ROWS/BMM, 1), 256, smG128>>>(attn, wp,
        nullptr, nullptr, bp, sa, nullptr, nullptr,
        ROWS, EE, EE, 0, 0, nullptr, nullptr);

    // 5) x1 = sa + sigmoid(sa @ wg_att + bg_att) * x
    mma_gemm<128,2,0><<<dim3(EE/128, ROWS/BMM, 1), 256, smG128>>>(sa, wg_att,
        nullptr, nullptr, bg_att, x1, nullptr, nullptr,
        ROWS, EE, EE, 0, 0, sa, x);

    // 6) h2 = LN2(x1)
    ln_kernel<<<ROWS, 256>>>(x1, ln2_g, ln2_b, h2);

    // 7) f1 = gelu(h2 @ w1 + b1)      [4096 x 4096]
    mma_gemm<128,1,0><<<dim3(4*EE/128, ROWS/BMM, 1), 256, smG128>>>(h2, w1,
        nullptr, nullptr, b1, f1, nullptr, nullptr,
        ROWS, 4*EE, EE, 0, 0, nullptr, nullptr);

    // 8) f2 = gelu(f1 @ w2 + b2)      [4096 x 2048], K=4096
    mma_gemm<128,1,0><<<dim3(2*EE/128, ROWS/BMM, 1), 256, smG128>>>(f1, w2,
        nullptr, nullptr, b2, f2, nullptr, nullptr,
        ROWS, 2*EE, 4*EE, 0, 0, nullptr, nullptr);

    // 9) f3 = f2 @ w3 + b3            [4096 x 1024], K=2048
    mma_gemm<128,0,0><<<dim3(EE/128, ROWS/BMM, 1), 256, smG128>>>(f2, w3,
        nullptr, nullptr, b3, f3, nullptr, nullptr,
        ROWS, EE, 2*EE, 0, 0, nullptr, nullptr);

    // 10) out_x = f3 + sigmoid(f3 @ wg_ff + bg_ff) * x1   (K = E)
    mma_gemm<128,2,0><<<dim3(EE/128, ROWS/BMM, 1), 256, smG128>>>(f3, wg_ff,
        nullptr, nullptr, bg_ff, out_x, nullptr, nullptr,
        ROWS, EE, EE, 0, 0, f3, x1);
}

// round 14
// speedup vs baseline: 3.0300x; 1.0817x over previous
#include <cuda_runtime.h>
#include <cuda_bf16.h>
#include <math.h>

// Problem constants
#define BB   2
#define TT   2048
#define EE   1024
#define HH   16
#define HS   64
#define ROWS (BB*TT)          // 4096

// ---------------- device scratch ----------------
__device__ float g_h1[ROWS*EE];
__device__ float g_q [ROWS*EE];
__device__ float g_k [ROWS*EE];
__device__ float g_v [ROWS*EE];
__device__ float g_attn[ROWS*EE];
__device__ float g_sa [ROWS*EE];
__device__ float g_x1 [ROWS*EE];
__device__ float g_h2 [ROWS*EE];
__device__ float g_f1 [ROWS*4*EE];
__device__ float g_f2 [ROWS*2*EE];
__device__ float g_f3 [ROWS*EE];
__device__ float g_L  [BB*HH*TT];
// tf32-rounded weight copies
__device__ float g_wq_r [HH*EE*HS];
__device__ float g_wk_r [HH*EE*HS];
__device__ float g_wv_r [HH*EE*HS];
__device__ float g_wp_r [EE*EE];
__device__ float g_wga_r[EE*EE];
__device__ float g_w1_r [EE*4*EE];
__device__ float g_w2_r [4*EE*2*EE];
__device__ float g_w3_r [2*EE*EE];
__device__ float g_wgf_r[EE*EE];

// ---------------- tf32 / cp.async helpers ----------------
__device__ __forceinline__ unsigned f2tf32(float f) {
    unsigned u;
    asm("cvt.rna.tf32.f32 %0, %1;" : "=r"(u) : "f"(f));
    return u;
}
__device__ __forceinline__ float rnd_tf32(float f) {
    return __uint_as_float(f2tf32(f));
}

__device__ __forceinline__ void mma_tf32(float* c, const unsigned* a,
                                         const unsigned* b) {
    asm volatile(
        "mma.sync.aligned.m16n8k8.row.col.f32.tf32.tf32.f32 "
        "{%0,%1,%2,%3}, {%4,%5,%6,%7}, {%8,%9}, {%0,%1,%2,%3};"
        : "+f"(c[0]), "+f"(c[1]), "+f"(c[2]), "+f"(c[3])
        : "r"(a[0]), "r"(a[1]), "r"(a[2]), "r"(a[3]),
          "r"(b[0]), "r"(b[1]));
}

__device__ __forceinline__ void cp_async16(void* smem_dst, const void* gsrc) {
    unsigned s = (unsigned)__cvta_generic_to_shared(smem_dst);
    asm volatile("cp.async.cg.shared.global [%0], [%1], 16;"
                 :: "r"(s), "l"(gsrc));
}
#define CP_COMMIT() asm volatile("cp.async.commit_group;" ::: "memory")
#define CP_WAIT0()  asm volatile("cp.async.wait_group 0;" ::: "memory")
#define CP_WAIT1()  asm volatile("cp.async.wait_group 1;" ::: "memory")

// ---------------- weight pre-rounding (tf32 rna) ----------------
__global__ void cvt_tf32_kernel(const float* __restrict__ in,
                                float* __restrict__ out, int n4) {
    int i = blockIdx.x * blockDim.x + threadIdx.x;
    if (i < n4) {
        float4 v = ((const float4*)in)[i];
        v.x = rnd_tf32(v.x); v.y = rnd_tf32(v.y);
        v.z = rnd_tf32(v.z); v.w = rnd_tf32(v.w);
        ((float4*)out)[i] = v;
    }
}

// ---------------- LayerNorm (tf32-rounded output) ----------------
__global__ void ln_kernel(const float* __restrict__ x,
                          const float* __restrict__ g,
                          const float* __restrict__ b,
                          float* __restrict__ out) {
    int row = blockIdx.x;
    int tid = threadIdx.x;                 // 256 threads, 4 floats each
    const float* xr = x + (size_t)row * EE;
    float4 v = *(const float4*)(xr + tid * 4);
    float s  = v.x + v.y + v.z + v.w;
    float ss = v.x*v.x + v.y*v.y + v.z*v.z + v.w*v.w;
    __shared__ float sm[32], sm2[32];
    int lane = tid & 31, warp = tid >> 5;
    #pragma unroll
    for (int o = 16; o > 0; o >>= 1) {
        s  += __shfl_down_sync(0xffffffffu, s,  o);
        ss += __shfl_down_sync(0xffffffffu, ss, o);
    }
    if (lane == 0) { sm[warp] = s; sm2[warp] = ss; }
    __syncthreads();
    if (warp == 0) {
        float a = (lane < 8) ? sm[lane]  : 0.f;
        float c = (lane < 8) ? sm2[lane] : 0.f;
        #pragma unroll
        for (int o = 4; o > 0; o >>= 1) {
            a += __shfl_down_sync(0xffffffffu, a, o);
            c += __shfl_down_sync(0xffffffffu, c, o);
        }
        if (lane == 0) { sm[0] = a; sm2[0] = c; }
    }
    __syncthreads();
    float mu  = sm[0]  * (1.0f / EE);
    float var = sm2[0] * (1.0f / EE) - mu * mu;
    float rstd = rsqrtf(var + 1e-5f);
    float4 gg = *(const float4*)(g + tid * 4);
    float4 bb = *(const float4*)(b + tid * 4);
    float4 o;
    o.x = rnd_tf32((v.x - mu) * rstd * gg.x + bb.x);
    o.y = rnd_tf32((v.y - mu) * rstd * gg.y + bb.y);
    o.z = rnd_tf32((v.z - mu) * rstd * gg.z + bb.z);
    o.w = rnd_tf32((v.w - mu) * rstd * gg.w + bb.w);
    *(float4*)(out + (size_t)row * EE + tid * 4) = o;
}

// ---------------- tf32 MMA GEMM, 3-stage cp.async pipeline ----------------
// All A/B operands are PRE-ROUNDED to tf32 -> raw bit loads, no inner CVT.
// RC: round stored C to tf32 (when C feeds a later MMA).
#define BMM 128
#define BKK 16
#define STG 3

template<int BN, int EPI, int QKV, int RC>
__global__ void __launch_bounds__((BN == 128) ? 256 : 128, (BN == 128) ? 2 : 3)
mma_gemm(const float* __restrict__ A,
         const float* __restrict__ B0, const float* __restrict__ B1,
         const float* __restrict__ B2,
         const float* __restrict__ bias,
         float* __restrict__ C0, float* __restrict__ C1,
         float* __restrict__ C2,
         int M, int N, int K, size_t bStrideZ, size_t cStrideZ,
         const float* __restrict__ other, const float* __restrict__ resid) {
    constexpr int THREADS = (BN == 128) ? 256 : 128;
    constexpr int NWN = BN / 32;            // warps along N
    constexpr int AP  = 20;                 // A smem pitch (words)
    constexpr int BP  = BN + 8;             // B smem pitch (words)
    constexpr int ASZ = BMM * AP;           // words per A stage
    constexpr int BSZ = BKK * BP;           // words per B stage
    constexpr int LA  = 512 / THREADS;      // A float4 per thread per stage
    constexpr int LB  = (BKK * BN / 4) / THREADS;
    constexpr int BNQ = BN / 4;

    extern __shared__ float dynsm[];
    float* As = dynsm;                      // [STG][ASZ]
    float* Bs = dynsm + STG * ASZ;          // [STG][BSZ]

    const float* Bp;
    float* Cp;
    if (QKV) {
        int zz = blockIdx.z;
        int which = zz >> 4, head = zz & 15;
        const float* Bsel = (which == 0) ? B0 : ((which == 1) ? B1 : B2);
        float*       Csel = (which == 0) ? C0 : ((which == 1) ? C1 : C2);
        Bp = Bsel + (size_t)head * bStrideZ;
        Cp = Csel + (size_t)head * cStrideZ;
    } else {
        Bp = B0; Cp = C0;
    }

    int m0 = blockIdx.y * BMM, n0 = blockIdx.x * BN;
    int tid  = threadIdx.x;
    int lane = tid & 31, warp = tid >> 5;
    int wm = warp / NWN, wn = warp % NWN;

    float acc[4][4][4];
    #pragma unroll
    for (int i = 0; i < 4; i++)
        #pragma unroll
        for (int j = 0; j < 4; j++)
            #pragma unroll
            for (int l = 0; l < 4; l++) acc[i][j][l] = 0.f;

    auto stage = [&](int s, int k0) {
        #pragma unroll
        for (int i = 0; i < LA; i++) {
            int idx = tid + i * THREADS;
            int r = idx >> 2, c4 = idx & 3;
            cp_async16(&As[s * ASZ + r * AP + c4 * 4],
                       A + (size_t)(m0 + r) * K + k0 + c4 * 4);
        }
        #pragma unroll
        for (int i = 0; i < LB; i++) {
            int idx = tid + i * THREADS;
            int r = idx / BNQ, c4 = idx % BNQ;
            cp_async16(&Bs[s * BSZ + r * BP + c4 * 4],
                       Bp + (size_t)(k0 + r) * N + n0 + c4 * 4);
        }
    };

    int nk = K / BKK;                       // >= 64 for all our shapes
    stage(0, 0);
    CP_COMMIT();                            // group: tile 0
    stage(1, BKK);
    CP_COMMIT();                            // group: tile 1

    for (int it = 0; it < nk; it++) {
        CP_WAIT1();                         // tile it landed
        __syncthreads();
        if (it + 2 < nk) stage((it + 2) % STG, (it + 2) * BKK);
        CP_COMMIT();                        // one group per iter (may be empty)

        const float* Asb = As + (it % STG) * ASZ;
        const float* Bsb = Bs + (it % STG) * BSZ;
        #pragma unroll
        for (int ks = 0; ks < BKK; ks += 8) {
            int lk = ks + (lane & 3);
            int lm = lane >> 2;
            unsigned a[4][4], b[4][2];
            #pragma unroll
            for (int mi = 0; mi < 4; mi++) {
                int m = wm * 64 + mi * 16 + lm;
                a[mi][0] = __float_as_uint(Asb[m * AP + lk]);
                a[mi][1] = __float_as_uint(Asb[(m + 8) * AP + lk]);
                a[mi][2] = __float_as_uint(Asb[m * AP + lk + 4]);
                a[mi][3] = __float_as_uint(Asb[(m + 8) * AP + lk + 4]);
            }
            #pragma unroll
            for (int ni = 0; ni < 4; ni++) {
                int n = wn * 32 + ni * 8 + lm;
                b[ni][0] = __float_as_uint(Bsb[lk * BP + n]);
                b[ni][1] = __float_as_uint(Bsb[(lk + 4) * BP + n]);
            }
            #pragma unroll
            for (int mi = 0; mi < 4; mi++)
                #pragma unroll
                for (int ni = 0; ni < 4; ni++)
                    mma_tf32(acc[mi][ni], a[mi], b[ni]);
        }
    }

    // ---------------- epilogue ----------------
    int gm = m0 + wm * 64;
    int gn = n0 + wn * 32;
    #pragma unroll
    for (int mi = 0; mi < 4; mi++) {
        #pragma unroll
        for (int half = 0; half < 2; half++) {
            int row = gm + mi * 16 + (lane >> 2) + half * 8;
            #pragma unroll
            for (int ni = 0; ni < 4; ni++) {
                int col = gn + ni * 8 + (lane & 3) * 2;
                float v0 = acc[mi][ni][half * 2 + 0];
                float v1 = acc[mi][ni][half * 2 + 1];
                if (bias) { v0 += bias[col]; v1 += bias[col + 1]; }
                size_t idx = (size_t)row * N + col;
                float2 o;
                if (EPI == 0) {
                    o = make_float2(v0, v1);
                } else if (EPI == 1) {
                    o.x = 0.5f * v0 * (1.0f + erff(v0 * 0.70710678118654752f));
                    o.y = 0.5f * v1 * (1.0f + erff(v1 * 0.70710678118654752f));
                } else {
                    float2 ot = *(const float2*)(other + idx);
                    float2 rs = *(const float2*)(resid + idx);
                    o.x = ot.x + rs.x / (1.0f + __expf(-v0));
                    o.y = ot.y + rs.y / (1.0f + __expf(-v1));
                }
                if (RC) { o.x = rnd_tf32(o.x); o.y = rnd_tf32(o.y); }
                *(float2*)(Cp + idx) = o;
            }
        }
    }
}

// ==================== MMA attention ====================
// Q/K/V pre-rounded to tf32 -> raw bit loads, no inner CVT.
// P rounded once at the Ps smem write.
#define QP 68
#define KPP 68
#define VPP 72
#define PPP 68

__device__ __forceinline__ void s_tile_mma(const float* __restrict__ Qs,
                                           const float* __restrict__ Ks,
                                           int wm, int wn, int lane,
                                           float acc[4][2][4]) {
    #pragma unroll
    for (int mi = 0; mi < 4; mi++)
        #pragma unroll
        for (int ni = 0; ni < 2; ni++)
            #pragma unroll
            for (int l = 0; l < 4; l++) acc[mi][ni][l] = 0.f;
    int lm = lane >> 2, lk = lane & 3;
    #pragma unroll
    for (int ks = 0; ks < 8; ks++) {
        int kb = ks * 8;
        unsigned a[4][4], b[2][2];
        #pragma unroll
        for (int mi = 0; mi < 4; mi++) {
            int m = wm * 64 + mi * 16 + lm;
            a[mi][0] = __float_as_uint(Qs[m * QP + kb + lk]);
            a[mi][1] = __float_as_uint(Qs[(m + 8) * QP + kb + lk]);
            a[mi][2] = __float_as_uint(Qs[m * QP + kb + lk + 4]);
            a[mi][3] = __float_as_uint(Qs[(m + 8) * QP + kb + lk + 4]);
        }
        #pragma unroll
        for (int ni = 0; ni < 2; ni++) {
            int n = wn * 16 + ni * 8 + lm;
            b[ni][0] = __float_as_uint(Ks[n * KPP + kb + lk]);
            b[ni][1] = __float_as_uint(Ks[n * KPP + kb + lk + 4]);
        }
        #pragma unroll
        for (int mi = 0; mi < 4; mi++)
            #pragma unroll
            for (int ni = 0; ni < 2; ni++)
                mma_tf32(acc[mi][ni], a[mi], b[ni]);
    }
}

// ---- Pass A: l[t] = sum_{s<=t} exp(score) ----
__global__ void __launch_bounds__(256)
attn_sum(const float* __restrict__ q, const float* __restrict__ k,
         float* __restrict__ Lb) {
    extern __shared__ float sm[];
    float* Qs   = sm;                     // 128*68
    float* Ks   = sm + 128 * QP;          // 64*68
    float* Lred = Ks + 64 * KPP;          // 128*4

    int bh = blockIdx.y;
    int qt = (int)(gridDim.x - 1) - (int)blockIdx.x;
    int b = bh >> 4, h = bh & 15;
    int qbase = qt * 128;
    const float* qg = q + ((size_t)h * ROWS + (size_t)b * TT + qbase) * HS;
    const float* kg = k + ((size_t)h * ROWS + (size_t)b * TT) * HS;

    int tid = threadIdx.x;
    int lane = tid & 31, warp = tid >> 5;
    int wm = warp >> 2, wn = warp & 3;
    int lm = lane >> 2, lk = lane & 3;

    // load Q tile
    #pragma unroll
    for (int i = 0; i < 8; i++) {
        int idx = tid + i * 256;
        int r = idx >> 4, c4 = idx & 15;
        cp_async16(&Qs[r * QP + c4 * 4], qg + (size_t)r * HS + c4 * 4);
    }
    CP_COMMIT();
    CP_WAIT0();
    __syncthreads();

    float lsum[4][2];
    #pragma unroll
    for (int mi = 0; mi < 4; mi++) { lsum[mi][0] = 0.f; lsum[mi][1] = 0.f; }

    int nkt = 2 * qt + 2;
    for (int kt = 0; kt < nkt; kt++) {
        __syncthreads();                 // previous iter done with Ks
        #pragma unroll
        for (int i = 0; i < 4; i++) {
            int idx = tid + i * 256;
            int r = idx >> 4, c4 = idx & 15;
            cp_async16(&Ks[r * KPP + c4 * 4],
                       kg + (size_t)(kt * 64 + r) * HS + c4 * 4);
        }
        CP_COMMIT();
        CP_WAIT0();
        __syncthreads();

        float acc[4][2][4];
        s_tile_mma(Qs, Ks, wm, wn, lane, acc);
        if (kt < 2 * qt) {               // fully unmasked fast path
            #pragma unroll
            for (int mi = 0; mi < 4; mi++)
                #pragma unroll
                for (int ni = 0; ni < 2; ni++) {
                    float* c = acc[mi][ni];
                    lsum[mi][0] += __expf(c[0] * 0.125f)
                                 + __expf(c[1] * 0.125f);
                    lsum[mi][1] += __expf(c[2] * 0.125f)
                                 + __expf(c[3] * 0.125f);
                }
        } else {                         // diagonal tiles: mask
            #pragma unroll
            for (int mi = 0; mi < 4; mi++) {
                int rq = qbase + wm * 64 + mi * 16 + lm;
                #pragma unroll
                for (int ni = 0; ni < 2; ni++) {
                    int kc = kt * 64 + wn * 16 + ni * 8 + 2 * lk;
                    float* c = acc[mi][ni];
                    if (kc     <= rq)     lsum[mi][0] += __expf(c[0] * 0.125f);
                    if (kc + 1 <= rq)     lsum[mi][0] += __expf(c[1] * 0.125f);
                    if (kc     <= rq + 8) lsum[mi][1] += __expf(c[2] * 0.125f);
                    if (kc + 1 <= rq + 8) lsum[mi][1] += __expf(c[3] * 0.125f);
                }
            }
        }
    }

    #pragma unroll
    for (int mi = 0; mi < 4; mi++)
        #pragma unroll
        for (int hf = 0; hf < 2; hf++) {
            float v = lsum[mi][hf];
            v += __shfl_xor_sync(0xffffffffu, v, 1);
            v += __shfl_xor_sync(0xffffffffu, v, 2);
            if (lk == 0)
                Lred[(wm * 64 + mi * 16 + lm + hf * 8) * 4 + wn] = v;
        }
    __syncthreads();
    if (tid < 128) {
        float l = Lred[tid * 4] + Lred[tid * 4 + 1] +
                  Lred[tid * 4 + 2] + Lred[tid * 4 + 3];
        Lb[(size_t)bh * TT + qbase + tid] = l;
    }
}

// ---- Pass B: wei + attn via MMA ----
__global__ void __launch_bounds__(256)
attn_out(const float* __restrict__ q, const float* __restrict__ k,
         const float* __restrict__ v, const float* __restrict__ Lb,
         float* __restrict__ wei, float* __restrict__ attn) {
    extern __shared__ float sm[];
    float* Qs = sm;                        // 128*68
    float* Ks = Qs + 128 * QP;             // 64*68
    float* Vs = Ks + 64 * KPP;             // 64*72
    float* Ps = Vs + 64 * VPP;             // 128*68

    int bh = blockIdx.y;
    int qt = (int)(gridDim.x - 1) - (int)blockIdx.x;
    int b = bh >> 4, h = bh & 15;
    int qbase = qt * 128;
    const float* qg = q + ((size_t)h * ROWS + (size_t)b * TT + qbase) * HS;
    const float* kg = k + ((size_t)h * ROWS + (size_t)b * TT) * HS;
    const float* vg = v + ((size_t)h * ROWS + (size_t)b * TT) * HS;
    float* weib = wei + ((size_t)bh * TT + qbase) * TT;

    int tid = threadIdx.x;
    int lane = tid & 31, warp = tid >> 5;
    int wm = warp >> 2, wn = warp & 3;
    int lm = lane >> 2, lk = lane & 3;

    // Q tile
    #pragma unroll
    for (int i = 0; i < 8; i++) {
        int idx = tid + i * 256;
        int r = idx >> 4, c4 = idx & 15;
        cp_async16(&Qs[r * QP + c4 * 4], qg + (size_t)r * HS + c4 * 4);
    }
    CP_COMMIT();

    float invl[4][2];
    #pragma unroll
    for (int mi = 0; mi < 4; mi++)
        #pragma unroll
        for (int hf = 0; hf < 2; hf++)
            invl[mi][hf] = 1.0f /
                Lb[(size_t)bh * TT + qbase + wm * 64 + mi * 16 + lm + hf * 8];

    float oacc[4][2][4];
    #pragma unroll
    for (int mi = 0; mi < 4; mi++)
        #pragma unroll
        for (int ni = 0; ni < 2; ni++)
            #pragma unroll
            for (int l = 0; l < 4; l++) oacc[mi][ni][l] = 0.f;

    CP_WAIT0();
    __syncthreads();

    int nkt = 2 * qt + 2;
    for (int kt = 0; kt < nkt; kt++) {
        __syncthreads();   // previous iter done with Ks/Vs/Ps
        // stage K and V together, single group
        #pragma unroll
        for (int i = 0; i < 4; i++) {
            int idx = tid + i * 256;
            int r = idx >> 4, c4 = idx & 15;
            cp_async16(&Ks[r * KPP + c4 * 4],
                       kg + (size_t)(kt * 64 + r) * HS + c4 * 4);
            cp_async16(&Vs[r * VPP + c4 * 4],
                       vg + (size_t)(kt * 64 + r) * HS + c4 * 4);
        }
        CP_COMMIT();
        CP_WAIT0();
        __syncthreads();

        float acc[4][2][4];
        s_tile_mma(Qs, Ks, wm, wn, lane, acc);

        // p = round_tf32(exp(s/8)/l) -> Ps (mask only on diagonal tiles)
        if (kt < 2 * qt) {
            #pragma unroll
            for (int mi = 0; mi < 4; mi++) {
                int r0 = wm * 64 + mi * 16 + lm;
                #pragma unroll
                for (int ni = 0; ni < 2; ni++) {
                    int cl = wn * 16 + ni * 8 + 2 * lk;
                    float* c = acc[mi][ni];
                    float2 p0, p1;
                    p0.x = rnd_tf32(__expf(c[0] * 0.125f) * invl[mi][0]);
                    p0.y = rnd_tf32(__expf(c[1] * 0.125f) * invl[mi][0]);
                    p1.x = rnd_tf32(__expf(c[2] * 0.125f) * invl[mi][1]);
                    p1.y = rnd_tf32(__expf(c[3] * 0.125f) * invl[mi][1]);
                    *(float2*)&Ps[r0 * PPP + cl] = p0;
                    *(float2*)&Ps[(r0 + 8) * PPP + cl] = p1;
                }
            }
        } else {
            #pragma unroll
            for (int mi = 0; mi < 4; mi++) {
                int r0 = wm * 64 + mi * 16 + lm;
                int rq0 = qbase + r0, rq1 = rq0 + 8;
                #pragma unroll
                for (int ni = 0; ni < 2; ni++) {
                    int cl = wn * 16 + ni * 8 + 2 * lk;
                    int kc = kt * 64 + cl;
                    float* c = acc[mi][ni];
                    float2 p0, p1;
                    p0.x = (kc     <= rq0)
                         ? rnd_tf32(__expf(c[0]*0.125f)*invl[mi][0]) : 0.f;
                    p0.y = (kc + 1 <= rq0)
                         ? rnd_tf32(__expf(c[1]*0.125f)*invl[mi][0]) : 0.f;
                    p1.x = (kc     <= rq1)
                         ? rnd_tf32(__expf(c[2]*0.125f)*invl[mi][1]) : 0.f;
                    p1.y = (kc + 1 <= rq1)
                         ? rnd_tf32(__expf(c[3]*0.125f)*invl[mi][1]) : 0.f;
                    *(float2*)&Ps[r0 * PPP + cl] = p0;
                    *(float2*)&Ps[(r0 + 8) * PPP + cl] = p1;
                }
            }
        }
        __syncthreads();     // Ps complete

        // coalesced copy Ps -> wei
        #pragma unroll
        for (int i = 0; i < 8; i++) {
            int idx = tid + i * 256;
            int r = idx >> 4, c4 = idx & 15;
            *(float4*)(weib + (size_t)r * TT + kt * 64 + c4 * 4) =
                *(const float4*)&Ps[r * PPP + c4 * 4];
        }

        // O += P * V  (k = 64 keys) — raw bit loads (P, V pre-rounded)
        #pragma unroll
        for (int ks = 0; ks < 8; ks++) {
            int kb = ks * 8;
            unsigned a[4][4], bfr[2][2];
            #pragma unroll
            for (int mi = 0; mi < 4; mi++) {
                int m = wm * 64 + mi * 16 + lm;
                a[mi][0] = __float_as_uint(Ps[m * PPP + kb + lk]);
                a[mi][1] = __float_as_uint(Ps[(m + 8) * PPP + kb + lk]);
                a[mi][2] = __float_as_uint(Ps[m * PPP + kb + lk + 4]);
                a[mi][3] = __float_as_uint(Ps[(m + 8) * PPP + kb + lk + 4]);
            }
            #pragma unroll
            for (int ni = 0; ni < 2; ni++) {
                int n = wn * 16 + ni * 8 + lm;
                bfr[ni][0] = __float_as_uint(Vs[(kb + lk) * VPP + n]);
                bfr[ni][1] = __float_as_uint(Vs[(kb + lk + 4) * VPP + n]);
            }
            #pragma unroll
            for (int mi = 0; mi < 4; mi++)
                #pragma unroll
                for (int ni = 0; ni < 2; ni++)
                    mma_tf32(oacc[mi][ni], a[mi], bfr[ni]);
        }
    }

    // zero-fill wei tail (cols >= nkt*64)
    int kend4 = nkt * 16;   // in float4 units
    float4 z4 = make_float4(0.f, 0.f, 0.f, 0.f);
    for (int r = tid >> 4; r < 128; r += 16)
        for (int c4 = kend4 + (tid & 15); c4 < TT / 4; c4 += 16)
            *(float4*)(weib + (size_t)r * TT + c4 * 4) = z4;

    // write attn output [row][h*HS + col] (tf32-rounded: feeds proj GEMM)
    float* attnb = attn + ((size_t)b * TT + qbase) * EE + h * HS;
    #pragma unroll
    for (int mi = 0; mi < 4; mi++) {
        int r0 = wm * 64 + mi * 16 + lm;
        #pragma unroll
        for (int ni = 0; ni < 2; ni++) {
            int col = wn * 16 + ni * 8 + 2 * lk;
            *(float2*)(attnb + (size_t)r0 * EE + col) =
                make_float2(rnd_tf32(oacc[mi][ni][0]),
                            rnd_tf32(oacc[mi][ni][1]));
            *(float2*)(attnb + (size_t)(r0 + 8) * EE + col) =
                make_float2(rnd_tf32(oacc[mi][ni][2]),
                            rnd_tf32(oacc[mi][ni][3]));
        }
    }
}

// ---------------- launch ----------------
extern "C" void kernel_launch(void* const* d_in, const int* in_sizes, int n_in,
                              void* d_out, int out_size) {
    const float* x      = (const float*)d_in[0];
    const float* wq     = (const float*)d_in[1];
    const float* wk     = (const float*)d_in[2];
    const float* wv     = (const float*)d_in[3];
    const float* wp     = (const float*)d_in[4];
    const float* bp     = (const float*)d_in[5];
    const float* ln1_g  = (const float*)d_in[6];
    const float* ln1_b  = (const float*)d_in[7];
    const float* ln2_g  = (const float*)d_in[8];
    const float* ln2_b  = (const float*)d_in[9];
    const float* w1     = (const float*)d_in[10];
    const float* b1     = (const float*)d_in[11];
    const float* w2     = (const float*)d_in[12];
    const float* b2     = (const float*)d_in[13];
    const float* w3     = (const float*)d_in[14];
    const float* b3     = (const float*)d_in[15];
    const float* wg_att = (const float*)d_in[16];
    const float* bg_att = (const float*)d_in[17];
    const float* wg_ff  = (const float*)d_in[18];
    const float* bg_ff  = (const float*)d_in[19];

    float* out_x   = (float*)d_out;                       // [B,T,E]
    float* out_wei = (float*)d_out + (size_t)ROWS * EE;   // [B,H,T,T]

    float *h1, *q, *k, *v, *attn, *sa, *x1, *h2, *f1, *f2, *f3, *Lb;
    float *wq_r, *wk_r, *wv_r, *wp_r, *wga_r, *w1_r, *w2_r, *w3_r, *wgf_r;
    cudaGetSymbolAddress((void**)&h1, g_h1);
    cudaGetSymbolAddress((void**)&q,  g_q);
    cudaGetSymbolAddress((void**)&k,  g_k);
    cudaGetSymbolAddress((void**)&v,  g_v);
    cudaGetSymbolAddress((void**)&attn, g_attn);
    cudaGetSymbolAddress((void**)&sa, g_sa);
    cudaGetSymbolAddress((void**)&x1, g_x1);
    cudaGetSymbolAddress((void**)&h2, g_h2);
    cudaGetSymbolAddress((void**)&f1, g_f1);
    cudaGetSymbolAddress((void**)&f2, g_f2);
    cudaGetSymbolAddress((void**)&f3, g_f3);
    cudaGetSymbolAddress((void**)&Lb, g_L);
    cudaGetSymbolAddress((void**)&wq_r,  g_wq_r);
    cudaGetSymbolAddress((void**)&wk_r,  g_wk_r);
    cudaGetSymbolAddress((void**)&wv_r,  g_wv_r);
    cudaGetSymbolAddress((void**)&wp_r,  g_wp_r);
    cudaGetSymbolAddress((void**)&wga_r, g_wga_r);
    cudaGetSymbolAddress((void**)&w1_r,  g_w1_r);
    cudaGetSymbolAddress((void**)&w2_r,  g_w2_r);
    cudaGetSymbolAddress((void**)&w3_r,  g_w3_r);
    cudaGetSymbolAddress((void**)&wgf_r, g_wgf_r);

    // dynamic smem sizes
    int smG64  = STG * (BMM * 20 + BKK * (64 + 8)) * 4;    // 44544
    int smG128 = STG * (BMM * 20 + BKK * (128 + 8)) * 4;   // 56832
    int smA = (128 * QP + 64 * KPP + 128 * 4) * 4;
    int smB = (128 * QP + 64 * KPP + 64 * VPP + 128 * PPP) * 4;
    cudaFuncSetAttribute(mma_gemm<64,0,1,1>,
        cudaFuncAttributeMaxDynamicSharedMemorySize, smG64);
    cudaFuncSetAttribute(mma_gemm<128,0,0,1>,
        cudaFuncAttributeMaxDynamicSharedMemorySize, smG128);
    cudaFuncSetAttribute(mma_gemm<128,1,0,1>,
        cudaFuncAttributeMaxDynamicSharedMemorySize, smG128);
    cudaFuncSetAttribute(mma_gemm<128,2,0,0>,
        cudaFuncAttributeMaxDynamicSharedMemorySize, smG128);
    cudaFuncSetAttribute(attn_sum,
        cudaFuncAttributeMaxDynamicSharedMemorySize, smA);
    cudaFuncSetAttribute(attn_out,
        cudaFuncAttributeMaxDynamicSharedMemorySize, smB);

    // 0) pre-round all weights to tf32 (epsilon-cost prologue)
    {
        int n1 = HH * EE * HS / 4;     // 262144
        cvt_tf32_kernel<<<n1 / 256, 256>>>(wq, wq_r, n1);
        cvt_tf32_kernel<<<n1 / 256, 256>>>(wk, wk_r, n1);
        cvt_tf32_kernel<<<n1 / 256, 256>>>(wv, wv_r, n1);
        int n2 = EE * EE / 4;          // 262144
        cvt_tf32_kernel<<<n2 / 256, 256>>>(wp, wp_r, n2);
        cvt_tf32_kernel<<<n2 / 256, 256>>>(wg_att, wga_r, n2);
        cvt_tf32_kernel<<<n2 / 256, 256>>>(wg_ff, wgf_r, n2);
        int n3 = EE * 4 * EE / 4;      // 1048576
        cvt_tf32_kernel<<<n3 / 256, 256>>>(w1, w1_r, n3);
        int n4 = 4 * EE * 2 * EE / 4;  // 2097152
        cvt_tf32_kernel<<<n4 / 256, 256>>>(w2, w2_r, n4);
        int n5 = 2 * EE * EE / 4;      // 524288
        cvt_tf32_kernel<<<n5 / 256, 256>>>(w3, w3_r, n5);
    }

    // 1) h1 = LN1(x)  (tf32-rounded)
    ln_kernel<<<ROWS, 256>>>(x, ln1_g, ln1_b, h1);

    // 2) fused q/k/v: z = 48 (3 weights x 16 heads)
    size_t wStrideZ = (size_t)EE * HS;
    size_t cStrideZ = (size_t)ROWS * HS;
    mma_gemm<64,0,1,1><<<dim3(1, ROWS/BMM, 48), 128, smG64>>>(h1, wq_r, wk_r,
        wv_r, nullptr, q, k, v, ROWS, HS, EE, wStrideZ, cStrideZ,
        nullptr, nullptr);

    // 3) attention (MMA, two-pass, no-max softmax)
    attn_sum<<<dim3(TT/128, BB*HH), 256, smA>>>(q, k, Lb);
    attn_out<<<dim3(TT/128, BB*HH), 256, smB>>>(q, k, v, Lb, out_wei, attn);

    // 4) sa = attn @ wp + bp   (rounded: feeds step 5)
    mma_gemm<128,0,0,1><<<dim3(EE/128, ROWS/BMM, 1), 256, smG128>>>(attn, wp_r,
        nullptr, nullptr, bp, sa, nullptr, nullptr,
        ROWS, EE, EE, 0, 0, nullptr, nullptr);

    // 5) x1 = sa + sigmoid(sa @ wg_att + bg_att) * x   (full fp32 out)
    mma_gemm<128,2,0,0><<<dim3(EE/128, ROWS/BMM, 1), 256, smG128>>>(sa, wga_r,
        nullptr, nullptr, bg_att, x1, nullptr, nullptr,
        ROWS, EE, EE, 0, 0, sa, x);

    // 6) h2 = LN2(x1)  (tf32-rounded)
    ln_kernel<<<ROWS, 256>>>(x1, ln2_g, ln2_b, h2);

    // 7) f1 = gelu(h2 @ w1 + b1)      [4096 x 4096] (rounded)
    mma_gemm<128,1,0,1><<<dim3(4*EE/128, ROWS/BMM, 1), 256, smG128>>>(h2, w1_r,
        nullptr, nullptr, b1, f1, nullptr, nullptr,
        ROWS, 4*EE, EE, 0, 0, nullptr, nullptr);

    // 8) f2 = gelu(f1 @ w2 + b2)      [4096 x 2048], K=4096 (rounded)
    mma_gemm<128,1,0,1><<<dim3(2*EE/128, ROWS/BMM, 1), 256, smG128>>>(f1, w2_r,
        nullptr, nullptr, b2, f2, nullptr, nullptr,
        ROWS, 2*EE, 4*EE, 0, 0, nullptr, nullptr);

    // 9) f3 = f2 @ w3 + b3            [4096 x 1024], K=2048 (rounded)
    mma_gemm<128,0,0,1><<<dim3(EE/128, ROWS/BMM, 1), 256, smG128>>>(f2, w3_r,
        nullptr, nullptr, b3, f3, nullptr, nullptr,
        ROWS, EE, 2*EE, 0, 0, nullptr, nullptr);

    // 10) out_x = f3 + sigmoid(f3 @ wg_ff + bg_ff) * x1   (K = E, fp32 out)
    mma_gemm<128,2,0,0><<<dim3(EE/128, ROWS/BMM, 1), 256, smG128>>>(f3, wgf_r,
        nullptr, nullptr, bg_ff, out_x, nullptr, nullptr,
        ROWS, EE, EE, 0, 0, f3, x1);
}